// round 12
// baseline (speedup 1.0000x reference)
#include <cuda_runtime.h>
#include <math.h>

#define N_NODES 100000
#define E_EDGES 1100000
#define HID 32
#define GF 8
#define NF 8

#define EBC ((E_EDGES + 255) / 256)   // edge-count blocks
#define NPB ((N_NODES + 255) / 256)   // per-node blocks

// ---------------- persistent device scratch ----------------
__device__ __align__(16) float d_hrc_l0[(size_t)N_NODES * 64];
__device__ __align__(16) float d_hrc_l1[(size_t)N_NODES * 64];
__device__ __align__(16) float d_hrc_l2[(size_t)N_NODES * 64];
__device__ __align__(16) float d_hrc_u[(size_t)N_NODES * 64];
__device__ __align__(16) float d_le[E_EDGES];
__device__ __align__(16) float d_ue[E_EDGES];
__device__ __align__(16) float d_ln[N_NODES * NF];
__device__ float d_agg[N_NODES];
__device__ float d_cntl[N_NODES];
__device__ float d_cntu[N_NODES];
__device__ float d_g[GF];
__device__ float d_nsum[GF];
__device__ float d_esum;
__device__ float d_hbase_e[HID];
__device__ float d_hbase_n[HID];
__device__ unsigned d_ncnt;

__inline__ __device__ float warpAllSum(float v) {
#pragma unroll
    for (int o = 16; o > 0; o >>= 1) v += __shfl_xor_sync(0xffffffffu, v, o);
    return v;
}

// ---------------- init ----------------
__global__ void k_zero(const float* __restrict__ eb1_0, const float* __restrict__ nb1_0) {
    int i = blockIdx.x * blockDim.x + threadIdx.x;
    if (i < N_NODES) {
        d_agg[i] = 0.f;
        d_cntl[i] = 0.f;
        d_cntu[i] = 0.f;
    }
    if (blockIdx.x == 0) {
        int j = threadIdx.x;
        if (j < HID) {
            d_hbase_e[j] = eb1_0[j];
            d_hbase_n[j] = nb1_0[j];
        }
        if (j < GF) { d_g[j] = 0.f; d_nsum[j] = 0.f; }
        if (j == 0) { d_esum = 0.f; d_ncnt = 0u; }
    }
}

// ---------------- prep body: hr = x @ W1[8:16], hc = x @ W1[16:24] ----------------
__device__ __forceinline__ void prep_body(int pb, int tid, float* sW,
                                          const float* __restrict__ xn,
                                          const float* __restrict__ W1,
                                          float* __restrict__ hrc) {
    for (int i = tid; i < 16 * HID; i += 256) sW[i] = W1[8 * HID + i];
    __syncthreads();

    int v = pb * 256 + tid;
    if (v >= N_NODES) return;
    const float4* xp = reinterpret_cast<const float4*>(xn + (size_t)v * 8);
    float4 x0 = xp[0], x1 = xp[1];
    float xv[8] = {x0.x, x0.y, x0.z, x0.w, x1.x, x1.y, x1.z, x1.w};

    float h[HID];
    float4* dst = reinterpret_cast<float4*>(hrc + (size_t)v * 64);
#pragma unroll
    for (int half = 0; half < 2; half++) {
#pragma unroll
        for (int j = 0; j < HID; j++) h[j] = 0.f;
#pragma unroll
        for (int k = 0; k < 8; k++) {
            float val = xv[k];
            const float4* wr = reinterpret_cast<const float4*>(&sW[(half * 8 + k) * HID]);
#pragma unroll
            for (int j4 = 0; j4 < HID / 4; j4++) {
                float4 w = wr[j4];
                h[j4 * 4 + 0] = fmaf(val, w.x, h[j4 * 4 + 0]);
                h[j4 * 4 + 1] = fmaf(val, w.y, h[j4 * 4 + 1]);
                h[j4 * 4 + 2] = fmaf(val, w.z, h[j4 * 4 + 2]);
                h[j4 * 4 + 3] = fmaf(val, w.w, h[j4 * 4 + 3]);
            }
        }
#pragma unroll
        for (int j4 = 0; j4 < HID / 4; j4++)
            dst[half * 8 + j4] = make_float4(h[j4 * 4], h[j4 * 4 + 1], h[j4 * 4 + 2], h[j4 * 4 + 3]);
    }
}

// ---------------- setup mega-kernel ----------------
__global__ __launch_bounds__(256) void k_setup(const int* __restrict__ lrow,
                                               const int* __restrict__ urow,
                                               const float* __restrict__ x,
                                               const float* __restrict__ eW1_0,
                                               const float* __restrict__ eW1_1,
                                               const float* __restrict__ eW1_2) {
    __shared__ __align__(16) float sW[16 * HID];
    int bid = blockIdx.x;
    int tid = threadIdx.x;
    if (bid < EBC) {
        int e = bid * 256 + tid;
        if (e < E_EDGES) {
            atomicAdd(&d_cntl[lrow[e]], 1.0f);
            atomicAdd(&d_cntu[urow[e]], 1.0f);
        }
    } else {
        int t = bid - EBC;
        int layer = t / NPB;
        int pb = t % NPB;
        const float* W1 = (layer == 0) ? eW1_0 : (layer == 1) ? eW1_1 : eW1_2;
        float* hrc = (layer == 0) ? d_hrc_l0 : (layer == 1) ? d_hrc_l1 : d_hrc_l2;
        prep_body(pb, tid, sW, x, W1, hrc);
    }
}

// ---------------- edge kernel: 8 lanes/edge, 4 edges per group-iteration ----------------
template <bool HAS_SKIP, bool WRITE_OUT, bool DO_AGG>
__global__ __launch_bounds__(256) void k_edge(
    const int* __restrict__ row, const int* __restrict__ col,
    const float* __restrict__ eprev, const float* __restrict__ eskip,
    const float* __restrict__ W1,   // 26x32 (rows 24,25 used)
    const float* __restrict__ W2,   // 32
    const float* __restrict__ B2,   // 1
    const float* __restrict__ hrc,  // N x 64 table
    float* __restrict__ ebuf,
    float* __restrict__ outp) {
    __shared__ float sred[8];
    int tid = threadIdx.x;
    int c = tid & 7;
    int g = tid >> 3;

    float base[4], w24[4], w25[4], w2[4];
#pragma unroll
    for (int i = 0; i < 4; i++) {
        base[i] = d_hbase_e[c * 4 + i];
        w24[i] = __ldg(&W1[24 * HID + c * 4 + i]);
        w25[i] = HAS_SKIP ? __ldg(&W1[25 * HID + c * 4 + i]) : 0.f;
        w2[i] = __ldg(&W2[c * 4 + i]);
    }
    float b2 = __ldg(B2);

    float esum_local = 0.f;
    const int step = gridDim.x * 128;
    for (int e0 = (blockIdx.x * 32 + g) * 4; e0 < E_EDGES; e0 += step) {
        int4 rr = *reinterpret_cast<const int4*>(&row[e0]);
        int4 cc = *reinterpret_cast<const int4*>(&col[e0]);
        float4 epv = *reinterpret_cast<const float4*>(&eprev[e0]);
        float4 esv = HAS_SKIP ? *reinterpret_cast<const float4*>(&eskip[e0])
                              : make_float4(0.f, 0.f, 0.f, 0.f);
        int r[4] = {rr.x, rr.y, rr.z, rr.w};
        int cl[4] = {cc.x, cc.y, cc.z, cc.w};
        float ep[4] = {epv.x, epv.y, epv.z, epv.w};
        float es[4] = {esv.x, esv.y, esv.z, esv.w};

        float4 hr[4], hc[4];
#pragma unroll
        for (int i = 0; i < 4; i++) {
            hr[i] = *reinterpret_cast<const float4*>(&hrc[(unsigned)r[i] * 64 + c * 4]);
            hc[i] = *reinterpret_cast<const float4*>(&hrc[(unsigned)cl[i] * 64 + 32 + c * 4]);
        }

        float p[4];
#pragma unroll
        for (int i = 0; i < 4; i++) {
            float t, q = 0.f;
            t = base[0] + hr[i].x + hc[i].x; t = fmaf(ep[i], w24[0], t); if (HAS_SKIP) t = fmaf(es[i], w25[0], t);
            q = fmaf(fmaxf(t, 0.f), w2[0], q);
            t = base[1] + hr[i].y + hc[i].y; t = fmaf(ep[i], w24[1], t); if (HAS_SKIP) t = fmaf(es[i], w25[1], t);
            q = fmaf(fmaxf(t, 0.f), w2[1], q);
            t = base[2] + hr[i].z + hc[i].z; t = fmaf(ep[i], w24[2], t); if (HAS_SKIP) t = fmaf(es[i], w25[2], t);
            q = fmaf(fmaxf(t, 0.f), w2[2], q);
            t = base[3] + hr[i].w + hc[i].w; t = fmaf(ep[i], w24[3], t); if (HAS_SKIP) t = fmaf(es[i], w25[3], t);
            q = fmaf(fmaxf(t, 0.f), w2[3], q);
            p[i] = q;
        }

#pragma unroll
        for (int i = 0; i < 4; i++) p[i] += __shfl_down_sync(0xffffffffu, p[i], 4);
#pragma unroll
        for (int i = 0; i < 4; i++) p[i] += __shfl_down_sync(0xffffffffu, p[i], 2);
#pragma unroll
        for (int i = 0; i < 4; i++) p[i] += __shfl_down_sync(0xffffffffu, p[i], 1);

        if (c == 0) {
            float o[4];
#pragma unroll
            for (int i = 0; i < 4; i++) o[i] = p[i] + b2;
            *reinterpret_cast<float4*>(&ebuf[e0]) = make_float4(o[0], o[1], o[2], o[3]);
            if (DO_AGG) {
#pragma unroll
                for (int i = 0; i < 4; i++) {
                    atomicAdd(&d_agg[r[i]], o[i]);
                    esum_local += o[i];
                }
            }
            if (WRITE_OUT) {
                float q[4];
#pragma unroll
                for (int i = 0; i < 4; i++) q[i] = (r[i] == cl[i]) ? expf(o[i]) : o[i];
                *reinterpret_cast<float4*>(&outp[e0]) = make_float4(q[0], q[1], q[2], q[3]);
            }
        }
    }

    if (DO_AGG) {
        float s = warpAllSum(esum_local);
        if ((tid & 31) == 0) sred[tid >> 5] = s;
        __syncthreads();
        if (tid < 8) {
            float v = sred[tid];
            v += __shfl_xor_sync(0xffu, v, 1);
            v += __shfl_xor_sync(0xffu, v, 2);
            v += __shfl_xor_sync(0xffu, v, 4);
            if (tid == 0) atomicAdd(&d_esum, v);
        }
    }
}

// ---------------- shared tail: block nsum reduce + fused global update ----------------
__device__ __forceinline__ void node_tail(int tid, const float* o, bool valid, float sred[8][NF],
                                          int* s_last, int grid,
                                          const float* __restrict__ gW1, const float* __restrict__ gB1,
                                          const float* __restrict__ gW2, const float* __restrict__ gB2,
                                          const float* __restrict__ neW1, const float* __restrict__ neB1,
                                          const float* __restrict__ nnW1, const float* __restrict__ nnB1) {
#pragma unroll
    for (int f = 0; f < NF; f++) {
        float contrib = valid ? o[f] : 0.f;
        float s = warpAllSum(contrib);
        if ((tid & 31) == 0) sred[tid >> 5][f] = s;
    }
    __syncthreads();
    if (tid < NF) {
        float s = 0.f;
#pragma unroll
        for (int w = 0; w < 8; w++) s += sred[w][tid];
        atomicAdd(&d_nsum[tid], s);
    }

    __syncthreads();
    if (tid == 0) {
        __threadfence();
        unsigned old = atomicAdd(&d_ncnt, 1u);
        *s_last = (old == (unsigned)grid - 1) ? 1 : 0;
    }
    __syncthreads();
    if (*s_last && tid < 32) {
        int j = tid;
        float in[17];
#pragma unroll
        for (int f = 0; f < NF; f++) in[f] = __ldcg(&d_nsum[f]) / (float)N_NODES;
        in[8] = __ldcg(&d_esum) / (float)E_EDGES;
#pragma unroll
        for (int f = 0; f < GF; f++) in[9 + f] = __ldcg(&d_g[f]);

        float h = gB1[j];
#pragma unroll
        for (int k = 0; k < 17; k++) h = fmaf(in[k], gW1[k * HID + j], h);
        h = fmaxf(h, 0.f);

        float gnew[GF];
#pragma unroll
        for (int f = 0; f < GF; f++) gnew[f] = __ldg(&gB2[f]) + warpAllSum(h * gW2[j * NF + f]);

        float be = neB1[j], bn = nnB1[j];
#pragma unroll
        for (int f = 0; f < GF; f++) {
            be = fmaf(gnew[f], neW1[f * HID + j], be);
            bn = fmaf(gnew[f], nnW1[f * HID + j], bn);
        }
        d_hbase_e[j] = be;
        d_hbase_n[j] = bn;

        if (j < GF) {
            d_g[j] = gnew[j];
            d_nsum[j] = 0.f;
        }
        if (j == 0) {
            d_esum = 0.f;
            d_ncnt = 0u;
        }
    }
}

// ---------------- node kernel: 1 thread/node (R4 measured-best) + fused global ----------------
template <bool FUSE_U>
__global__ __launch_bounds__(256) void k_node(
    const float* __restrict__ xn,   // N x 8 (x or ln)
    const float* __restrict__ cnt,  // N
    const float* __restrict__ W1,   // 17 x 32 (rows 8..16 used)
    const float* __restrict__ W2,   // 32 x 8
    const float* __restrict__ B2,   // 8
    const float* __restrict__ uW1,  // next (upper) edge W1, rows 8..24 (FUSE_U)
    const float* __restrict__ gW1, const float* __restrict__ gB1,
    const float* __restrict__ gW2, const float* __restrict__ gB2,
    const float* __restrict__ neW1, const float* __restrict__ neB1,
    const float* __restrict__ nnW1, const float* __restrict__ nnB1) {
    __shared__ __align__(16) float sW1[9 * HID];
    __shared__ __align__(16) float sW2[HID * NF];
    __shared__ __align__(16) float sUW[16 * HID];
    __shared__ float sB2[NF];
    __shared__ float sbase[HID];
    __shared__ float sred[8][NF];
    __shared__ int s_last;

    int tid = threadIdx.x;
    for (int i = tid; i < 9 * HID; i += 256) sW1[i] = W1[8 * HID + i];
    for (int i = tid; i < HID * NF; i += 256) sW2[i] = W2[i];
    if (FUSE_U)
        for (int i = tid; i < 16 * HID; i += 256) sUW[i] = uW1[8 * HID + i];
    if (tid < HID) sbase[tid] = d_hbase_n[tid];
    if (tid < NF) sB2[tid] = B2[tid];
    __syncthreads();

    int v = blockIdx.x * 256 + tid;
    float o[NF];
#pragma unroll
    for (int f = 0; f < NF; f++) o[f] = 0.f;
    bool valid = (v < N_NODES);

    if (valid) {
        const float4* xp = reinterpret_cast<const float4*>(xn + (size_t)v * 8);
        float4 x0 = xp[0], x1 = xp[1];
        float xv[8] = {x0.x, x0.y, x0.z, x0.w, x1.x, x1.y, x1.z, x1.w};
        float a = d_agg[v] / fmaxf(cnt[v], 1.0f);
        d_agg[v] = 0.f;  // recycle for next pass

        float h[HID];
#pragma unroll
        for (int j = 0; j < HID; j++) h[j] = sbase[j];
#pragma unroll
        for (int k = 0; k < 9; k++) {
            float val = (k < 8) ? xv[k] : a;
            const float4* wr = reinterpret_cast<const float4*>(&sW1[k * HID]);
#pragma unroll
            for (int j4 = 0; j4 < HID / 4; j4++) {
                float4 w = wr[j4];
                h[j4 * 4 + 0] = fmaf(val, w.x, h[j4 * 4 + 0]);
                h[j4 * 4 + 1] = fmaf(val, w.y, h[j4 * 4 + 1]);
                h[j4 * 4 + 2] = fmaf(val, w.z, h[j4 * 4 + 2]);
                h[j4 * 4 + 3] = fmaf(val, w.w, h[j4 * 4 + 3]);
            }
        }
#pragma unroll
        for (int f = 0; f < NF; f++) o[f] = sB2[f];
#pragma unroll
        for (int j = 0; j < HID; j++) {
            float r = fmaxf(h[j], 0.f);
            const float4* wr = reinterpret_cast<const float4*>(&sW2[j * NF]);
            float4 w0 = wr[0], w1 = wr[1];
            o[0] = fmaf(r, w0.x, o[0]); o[1] = fmaf(r, w0.y, o[1]);
            o[2] = fmaf(r, w0.z, o[2]); o[3] = fmaf(r, w0.w, o[3]);
            o[4] = fmaf(r, w1.x, o[4]); o[5] = fmaf(r, w1.y, o[5]);
            o[6] = fmaf(r, w1.z, o[6]); o[7] = fmaf(r, w1.w, o[7]);
        }

        if (FUSE_U) {
            float4* lnp = reinterpret_cast<float4*>(&d_ln[(size_t)v * 8]);
            lnp[0] = make_float4(o[0], o[1], o[2], o[3]);
            lnp[1] = make_float4(o[4], o[5], o[6], o[7]);
            float4* dst = reinterpret_cast<float4*>(&d_hrc_u[(size_t)v * 64]);
#pragma unroll
            for (int half = 0; half < 2; half++) {
                float t[HID];
#pragma unroll
                for (int j = 0; j < HID; j++) t[j] = 0.f;
#pragma unroll
                for (int k = 0; k < 8; k++) {
                    float val = o[k];
                    const float4* wr = reinterpret_cast<const float4*>(&sUW[(half * 8 + k) * HID]);
#pragma unroll
                    for (int j4 = 0; j4 < HID / 4; j4++) {
                        float4 w = wr[j4];
                        t[j4 * 4 + 0] = fmaf(val, w.x, t[j4 * 4 + 0]);
                        t[j4 * 4 + 1] = fmaf(val, w.y, t[j4 * 4 + 1]);
                        t[j4 * 4 + 2] = fmaf(val, w.z, t[j4 * 4 + 2]);
                        t[j4 * 4 + 3] = fmaf(val, w.w, t[j4 * 4 + 3]);
                    }
                }
#pragma unroll
                for (int j4 = 0; j4 < HID / 4; j4++)
                    dst[half * 8 + j4] = make_float4(t[j4 * 4], t[j4 * 4 + 1], t[j4 * 4 + 2], t[j4 * 4 + 3]);
            }
        }
    }

    node_tail(tid, o, valid, sred, &s_last, gridDim.x,
              gW1, gB1, gW2, gB2, neW1, neB1, nnW1, nnB1);
}

// ---------------- host launch ----------------
extern "C" void kernel_launch(void* const* d_in, const int* in_sizes, int n_in,
                              void* d_out, int out_size) {
    const float* x = (const float*)d_in[0];
    const int* lei = (const int*)d_in[1];
    const int* uei = (const int*)d_in[2];
    const float* lattr = (const float*)d_in[3];
    const float* uattr = (const float*)d_in[4];
    const float* eW1 = (const float*)d_in[5];
    const float* eb1 = (const float*)d_in[6];
    const float* eW2 = (const float*)d_in[7];
    const float* eb2 = (const float*)d_in[8];
    const float* nW1 = (const float*)d_in[9];
    const float* nb1 = (const float*)d_in[10];
    const float* nW2 = (const float*)d_in[11];
    const float* nb2 = (const float*)d_in[12];
    const float* gW1 = (const float*)d_in[13];
    const float* gb1 = (const float*)d_in[14];
    const float* gW2 = (const float*)d_in[15];
    const float* gb2 = (const float*)d_in[16];
    float* outp = (float*)d_out;

    const int* lrow = lei;
    const int* lcol = lei + E_EDGES;
    const int* urow = uei;
    const int* ucol = uei + E_EDGES;

    float *p_le, *p_ue, *p_ln, *p_cntl, *p_cntu, *p_hl0, *p_hl1, *p_hl2, *p_hu;
    cudaGetSymbolAddress((void**)&p_le, d_le);
    cudaGetSymbolAddress((void**)&p_ue, d_ue);
    cudaGetSymbolAddress((void**)&p_ln, d_ln);
    cudaGetSymbolAddress((void**)&p_cntl, d_cntl);
    cudaGetSymbolAddress((void**)&p_cntu, d_cntu);
    cudaGetSymbolAddress((void**)&p_hl0, d_hrc_l0);
    cudaGetSymbolAddress((void**)&p_hl1, d_hrc_l1);
    cudaGetSymbolAddress((void**)&p_hl2, d_hrc_l2);
    cudaGetSymbolAddress((void**)&p_hu, d_hrc_u);
    float* p_hl[3] = {p_hl0, p_hl1, p_hl2};

    const int EGB = 1184;

#define EW1P(b, i) (eW1 + (size_t)((b)*3 + (i)) * 26 * HID)
#define EB1P(b, i) (eb1 + ((b)*3 + (i)) * HID)
#define EW2P(b, i) (eW2 + ((b)*3 + (i)) * HID)
#define EB2P(b, i) (eb2 + ((b)*3 + (i)))
#define NW1P(b, i) (nW1 + (size_t)((b)*3 + (i)) * 17 * HID)
#define NB1P(b, i) (nb1 + ((b)*3 + (i)) * HID)
#define NW2P(b, i) (nW2 + (size_t)((b)*3 + (i)) * HID * NF)
#define NB2P(b, i) (nb2 + ((b)*3 + (i)) * NF)
#define GWP(b, i) gW1 + (size_t)((b)*3 + (i)) * 17 * HID, gb1 + ((b)*3 + (i)) * HID, \
                  gW2 + (size_t)((b)*3 + (i)) * HID * NF, gb2 + ((b)*3 + (i)) * NF

    k_zero<<<NPB, 256>>>(EB1P(0, 0), NB1P(0, 0));
    k_setup<<<EBC + 3 * NPB, 256>>>(lrow, urow, x, EW1P(0, 0), EW1P(0, 1), EW1P(0, 2));

    for (int i = 0; i < 3; i++) {
        const float* le_prev = (i == 0) ? lattr : p_le;
        const float* ue_prev = (i == 0) ? uattr : p_ue;
        bool last = (i == 2);

        if (i == 0)
            k_edge<false, false, true><<<EGB, 256>>>(lrow, lcol, le_prev, lattr, EW1P(0, i), EW2P(0, i), EB2P(0, i), p_hl[i], p_le, outp);
        else if (!last)
            k_edge<true, false, true><<<EGB, 256>>>(lrow, lcol, le_prev, lattr, EW1P(0, i), EW2P(0, i), EB2P(0, i), p_hl[i], p_le, outp);
        else
            k_edge<true, true, true><<<EGB, 256>>>(lrow, lcol, le_prev, lattr, EW1P(0, i), EW2P(0, i), EB2P(0, i), p_hl[i], p_le, outp);

        k_node<true><<<NPB, 256>>>(x, p_cntl, NW1P(0, i), NW2P(0, i), NB2P(0, i), EW1P(1, i),
                                   GWP(0, i), EW1P(1, i), EB1P(1, i), NW1P(1, i), NB1P(1, i));

        if (!last)
            k_edge<false, false, true><<<EGB, 256>>>(urow, ucol, ue_prev, uattr, EW1P(1, i), EW2P(1, i), EB2P(1, i), p_hu, p_ue, outp);
        else
            k_edge<false, true, false><<<EGB, 256>>>(urow, ucol, ue_prev, uattr, EW1P(1, i), EW2P(1, i), EB2P(1, i), p_hu, p_ue,
                                                     outp + E_EDGES);

        if (!last)
            k_node<false><<<NPB, 256>>>(p_ln, p_cntu, NW1P(1, i), NW2P(1, i), NB2P(1, i), EW1P(1, i),
                                        GWP(1, i), EW1P(0, i + 1), EB1P(0, i + 1), NW1P(0, i + 1), NB1P(0, i + 1));
    }

#undef EW1P
#undef EB1P
#undef EW2P
#undef EB2P
#undef NW1P
#undef NB1P
#undef NW2P
#undef NB2P
#undef GWP
}

// round 13
// speedup vs baseline: 1.3604x; 1.3604x over previous
#include <cuda_runtime.h>
#include <math.h>

#define N_NODES 100000
#define E_EDGES 1100000
#define HID 32
#define GF 8
#define NF 8

#define EBC ((E_EDGES + 255) / 256)   // edge-count blocks
#define NPB ((N_NODES + 255) / 256)   // per-node prep blocks (256 thr)
#define NHB 391                        // node blocks: 128 thr, 2 nodes/thread (391*128=50048)
#define NSPLIT 50048                   // second node = v + NSPLIT

// ---------------- persistent device scratch ----------------
__device__ __align__(16) float d_hrc_l0[(size_t)N_NODES * 64];
__device__ __align__(16) float d_hrc_l1[(size_t)N_NODES * 64];
__device__ __align__(16) float d_hrc_l2[(size_t)N_NODES * 64];
__device__ __align__(16) float d_hrc_u[(size_t)N_NODES * 64];
__device__ __align__(16) float d_le[E_EDGES];
__device__ __align__(16) float d_ue[E_EDGES];
__device__ __align__(16) float d_ln[N_NODES * NF];
__device__ float d_agg[N_NODES];
__device__ float d_cntl[N_NODES];
__device__ float d_cntu[N_NODES];
__device__ float d_g[GF];
__device__ float d_nsum[GF];
__device__ float d_esum;
__device__ float d_hbase_e[HID];
__device__ float d_hbase_n[HID];
__device__ unsigned d_ncnt;

__inline__ __device__ float warpAllSum(float v) {
#pragma unroll
    for (int o = 16; o > 0; o >>= 1) v += __shfl_xor_sync(0xffffffffu, v, o);
    return v;
}

__inline__ __device__ void l2_prefetch(const void* p) {
    asm volatile("prefetch.global.L2 [%0];" :: "l"(p));
}

// ---------------- init ----------------
__global__ void k_zero(const float* __restrict__ eb1_0, const float* __restrict__ nb1_0) {
    int i = blockIdx.x * blockDim.x + threadIdx.x;
    if (i < N_NODES) {
        d_agg[i] = 0.f;
        d_cntl[i] = 0.f;
        d_cntu[i] = 0.f;
    }
    if (blockIdx.x == 0) {
        int j = threadIdx.x;
        if (j < HID) {
            d_hbase_e[j] = eb1_0[j];
            d_hbase_n[j] = nb1_0[j];
        }
        if (j < GF) { d_g[j] = 0.f; d_nsum[j] = 0.f; }
        if (j == 0) { d_esum = 0.f; d_ncnt = 0u; }
    }
}

// ---------------- prep body: hr = x @ W1[8:16], hc = x @ W1[16:24] ----------------
__device__ __forceinline__ void prep_body(int pb, int tid, float* sW,
                                          const float* __restrict__ xn,
                                          const float* __restrict__ W1,
                                          float* __restrict__ hrc) {
    for (int i = tid; i < 16 * HID; i += 256) sW[i] = W1[8 * HID + i];
    __syncthreads();

    int v = pb * 256 + tid;
    if (v >= N_NODES) return;
    const float4* xp = reinterpret_cast<const float4*>(xn + (size_t)v * 8);
    float4 x0 = xp[0], x1 = xp[1];
    float xv[8] = {x0.x, x0.y, x0.z, x0.w, x1.x, x1.y, x1.z, x1.w};

    float h[HID];
    float4* dst = reinterpret_cast<float4*>(hrc + (size_t)v * 64);
#pragma unroll
    for (int half = 0; half < 2; half++) {
#pragma unroll
        for (int j = 0; j < HID; j++) h[j] = 0.f;
#pragma unroll
        for (int k = 0; k < 8; k++) {
            float val = xv[k];
            const float4* wr = reinterpret_cast<const float4*>(&sW[(half * 8 + k) * HID]);
#pragma unroll
            for (int j4 = 0; j4 < HID / 4; j4++) {
                float4 w = wr[j4];
                h[j4 * 4 + 0] = fmaf(val, w.x, h[j4 * 4 + 0]);
                h[j4 * 4 + 1] = fmaf(val, w.y, h[j4 * 4 + 1]);
                h[j4 * 4 + 2] = fmaf(val, w.z, h[j4 * 4 + 2]);
                h[j4 * 4 + 3] = fmaf(val, w.w, h[j4 * 4 + 3]);
            }
        }
#pragma unroll
        for (int j4 = 0; j4 < HID / 4; j4++)
            dst[half * 8 + j4] = make_float4(h[j4 * 4], h[j4 * 4 + 1], h[j4 * 4 + 2], h[j4 * 4 + 3]);
    }
}

// ---------------- setup mega-kernel ----------------
__global__ __launch_bounds__(256) void k_setup(const int* __restrict__ lrow,
                                               const int* __restrict__ urow,
                                               const float* __restrict__ x,
                                               const float* __restrict__ eW1_0,
                                               const float* __restrict__ eW1_1,
                                               const float* __restrict__ eW1_2) {
    __shared__ __align__(16) float sW[16 * HID];
    int bid = blockIdx.x;
    int tid = threadIdx.x;
    if (bid < EBC) {
        int e = bid * 256 + tid;
        if (e < E_EDGES) {
            atomicAdd(&d_cntl[lrow[e]], 1.0f);
            atomicAdd(&d_cntu[urow[e]], 1.0f);
        }
    } else {
        int t = bid - EBC;
        int layer = t / NPB;
        int pb = t % NPB;
        const float* W1 = (layer == 0) ? eW1_0 : (layer == 1) ? eW1_1 : eW1_2;
        float* hrc = (layer == 0) ? d_hrc_l0 : (layer == 1) ? d_hrc_l1 : d_hrc_l2;
        prep_body(pb, tid, sW, x, W1, hrc);
    }
}

// ---------------- edge kernel: 8 lanes/edge, 4 edges per group-iteration ----------------
template <bool HAS_SKIP, bool WRITE_OUT, bool DO_AGG>
__global__ __launch_bounds__(256) void k_edge(
    const int* __restrict__ row, const int* __restrict__ col,
    const float* __restrict__ eprev, const float* __restrict__ eskip,
    const float* __restrict__ W1,   // 26x32 (rows 24,25 used)
    const float* __restrict__ W2,   // 32
    const float* __restrict__ B2,   // 1
    const float* __restrict__ hrc,  // N x 64 table
    float* __restrict__ ebuf,
    float* __restrict__ outp) {
    __shared__ float sred[8];
    int tid = threadIdx.x;
    int c = tid & 7;
    int g = tid >> 3;

    float base[4], w24[4], w25[4], w2[4];
#pragma unroll
    for (int i = 0; i < 4; i++) {
        base[i] = d_hbase_e[c * 4 + i];
        w24[i] = __ldg(&W1[24 * HID + c * 4 + i]);
        w25[i] = HAS_SKIP ? __ldg(&W1[25 * HID + c * 4 + i]) : 0.f;
        w2[i] = __ldg(&W2[c * 4 + i]);
    }
    float b2 = __ldg(B2);

    float esum_local = 0.f;
    const int step = gridDim.x * 128;
    for (int e0 = (blockIdx.x * 32 + g) * 4; e0 < E_EDGES; e0 += step) {
        int4 rr = *reinterpret_cast<const int4*>(&row[e0]);
        int4 cc = *reinterpret_cast<const int4*>(&col[e0]);
        float4 epv = *reinterpret_cast<const float4*>(&eprev[e0]);
        float4 esv = HAS_SKIP ? *reinterpret_cast<const float4*>(&eskip[e0])
                              : make_float4(0.f, 0.f, 0.f, 0.f);
        int r[4] = {rr.x, rr.y, rr.z, rr.w};
        int cl[4] = {cc.x, cc.y, cc.z, cc.w};
        float ep[4] = {epv.x, epv.y, epv.z, epv.w};
        float es[4] = {esv.x, esv.y, esv.z, esv.w};

        float4 hr[4], hc[4];
#pragma unroll
        for (int i = 0; i < 4; i++) {
            hr[i] = *reinterpret_cast<const float4*>(&hrc[(unsigned)r[i] * 64 + c * 4]);
            hc[i] = *reinterpret_cast<const float4*>(&hrc[(unsigned)cl[i] * 64 + 32 + c * 4]);
        }

        float p[4];
#pragma unroll
        for (int i = 0; i < 4; i++) {
            float t, q = 0.f;
            t = base[0] + hr[i].x + hc[i].x; t = fmaf(ep[i], w24[0], t); if (HAS_SKIP) t = fmaf(es[i], w25[0], t);
            q = fmaf(fmaxf(t, 0.f), w2[0], q);
            t = base[1] + hr[i].y + hc[i].y; t = fmaf(ep[i], w24[1], t); if (HAS_SKIP) t = fmaf(es[i], w25[1], t);
            q = fmaf(fmaxf(t, 0.f), w2[1], q);
            t = base[2] + hr[i].z + hc[i].z; t = fmaf(ep[i], w24[2], t); if (HAS_SKIP) t = fmaf(es[i], w25[2], t);
            q = fmaf(fmaxf(t, 0.f), w2[2], q);
            t = base[3] + hr[i].w + hc[i].w; t = fmaf(ep[i], w24[3], t); if (HAS_SKIP) t = fmaf(es[i], w25[3], t);
            q = fmaf(fmaxf(t, 0.f), w2[3], q);
            p[i] = q;
        }

#pragma unroll
        for (int i = 0; i < 4; i++) p[i] += __shfl_down_sync(0xffffffffu, p[i], 4);
#pragma unroll
        for (int i = 0; i < 4; i++) p[i] += __shfl_down_sync(0xffffffffu, p[i], 2);
#pragma unroll
        for (int i = 0; i < 4; i++) p[i] += __shfl_down_sync(0xffffffffu, p[i], 1);

        if (c == 0) {
            float o[4];
#pragma unroll
            for (int i = 0; i < 4; i++) o[i] = p[i] + b2;
            *reinterpret_cast<float4*>(&ebuf[e0]) = make_float4(o[0], o[1], o[2], o[3]);
            if (DO_AGG) {
#pragma unroll
                for (int i = 0; i < 4; i++) {
                    atomicAdd(&d_agg[r[i]], o[i]);
                    esum_local += o[i];
                }
            }
            if (WRITE_OUT) {
                float q[4];
#pragma unroll
                for (int i = 0; i < 4; i++) q[i] = (r[i] == cl[i]) ? expf(o[i]) : o[i];
                *reinterpret_cast<float4*>(&outp[e0]) = make_float4(q[0], q[1], q[2], q[3]);
            }
        }
    }

    if (DO_AGG) {
        float s = warpAllSum(esum_local);
        if ((tid & 31) == 0) sred[tid >> 5] = s;
        __syncthreads();
        if (tid < 8) {
            float v = sred[tid];
            v += __shfl_xor_sync(0xffu, v, 1);
            v += __shfl_xor_sync(0xffu, v, 2);
            v += __shfl_xor_sync(0xffu, v, 4);
            if (tid == 0) atomicAdd(&d_esum, v);
        }
    }
}

// ---------------- node kernel: 128 threads, 2 nodes/thread + fused global ----------------
template <bool FUSE_U>
__global__ __launch_bounds__(128) void k_node(
    const float* __restrict__ xn,   // N x 8 (x or ln)
    const float* __restrict__ cnt,  // N
    const float* __restrict__ W1,   // 17 x 32 (rows 8..16 used)
    const float* __restrict__ W2,   // 32 x 8
    const float* __restrict__ B2,   // 8
    const float* __restrict__ uW1,  // next (upper) edge W1, rows 8..24 (FUSE_U)
    const float* __restrict__ gW1, const float* __restrict__ gB1,
    const float* __restrict__ gW2, const float* __restrict__ gB2,
    const float* __restrict__ neW1, const float* __restrict__ neB1,
    const float* __restrict__ nnW1, const float* __restrict__ nnB1) {
    __shared__ __align__(16) float sW1[9 * HID];
    __shared__ __align__(16) float sW2[HID * NF];
    __shared__ __align__(16) float sUW[16 * HID];
    __shared__ float sB2[NF];
    __shared__ float sbase[HID];
    __shared__ float sred[4][NF];
    __shared__ int s_last;

    int tid = threadIdx.x;
    for (int i = tid; i < 9 * HID; i += 128) sW1[i] = W1[8 * HID + i];
    for (int i = tid; i < HID * NF; i += 128) sW2[i] = W2[i];
    if (FUSE_U)
        for (int i = tid; i < 16 * HID; i += 128) sUW[i] = uW1[8 * HID + i];
    if (tid < HID) sbase[tid] = d_hbase_n[tid];
    if (tid < NF) sB2[tid] = B2[tid];
    // warm L2 for the fused-global tail so the last block doesn't eat cold-LDG latency
    if (tid < 17) l2_prefetch(gW1 + tid * 32);
    else if (tid < 25) l2_prefetch(gW2 + (tid - 17) * 32);
    else if (tid < 33) l2_prefetch(neW1 + (tid - 25) * 32);
    else if (tid < 41) l2_prefetch(nnW1 + (tid - 33) * 32);
    else if (tid == 41) l2_prefetch(gB1);
    else if (tid == 42) l2_prefetch(neB1);
    else if (tid == 43) l2_prefetch(nnB1);
    else if (tid == 44) l2_prefetch(gB2);
    __syncthreads();

    int vA = blockIdx.x * 128 + tid;   // always < NSPLIT <= N_NODES
    int vB = vA + NSPLIT;
    bool valB = (vB < N_NODES);

    // ---- load inputs for both nodes ----
    const float4* xpA = reinterpret_cast<const float4*>(xn + (size_t)vA * 8);
    float4 xA0 = xpA[0], xA1 = xpA[1];
    float aA = d_agg[vA] / fmaxf(cnt[vA], 1.0f);
    d_agg[vA] = 0.f;
    float4 xB0 = make_float4(0.f, 0.f, 0.f, 0.f), xB1 = xB0;
    float aB = 0.f;
    if (valB) {
        const float4* xpB = reinterpret_cast<const float4*>(xn + (size_t)vB * 8);
        xB0 = xpB[0]; xB1 = xpB[1];
        aB = d_agg[vB] / fmaxf(cnt[vB], 1.0f);
        d_agg[vB] = 0.f;
    }
    float xvA[8] = {xA0.x, xA0.y, xA0.z, xA0.w, xA1.x, xA1.y, xA1.z, xA1.w};
    float xvB[8] = {xB0.x, xB0.y, xB0.z, xB0.w, xB1.x, xB1.y, xB1.z, xB1.w};

    // ---- layer 1: shared weight loads feed two independent chains ----
    float hA[HID], hB[HID];
#pragma unroll
    for (int j = 0; j < HID; j++) { hA[j] = sbase[j]; hB[j] = sbase[j]; }
#pragma unroll
    for (int k = 0; k < 9; k++) {
        float va = (k < 8) ? xvA[k] : aA;
        float vb = (k < 8) ? xvB[k] : aB;
        const float4* wr = reinterpret_cast<const float4*>(&sW1[k * HID]);
#pragma unroll
        for (int j4 = 0; j4 < HID / 4; j4++) {
            float4 w = wr[j4];
            hA[j4 * 4 + 0] = fmaf(va, w.x, hA[j4 * 4 + 0]);
            hB[j4 * 4 + 0] = fmaf(vb, w.x, hB[j4 * 4 + 0]);
            hA[j4 * 4 + 1] = fmaf(va, w.y, hA[j4 * 4 + 1]);
            hB[j4 * 4 + 1] = fmaf(vb, w.y, hB[j4 * 4 + 1]);
            hA[j4 * 4 + 2] = fmaf(va, w.z, hA[j4 * 4 + 2]);
            hB[j4 * 4 + 2] = fmaf(vb, w.z, hB[j4 * 4 + 2]);
            hA[j4 * 4 + 3] = fmaf(va, w.w, hA[j4 * 4 + 3]);
            hB[j4 * 4 + 3] = fmaf(vb, w.w, hB[j4 * 4 + 3]);
        }
    }

    // ---- layer 2 ----
    float oA[NF], oB[NF];
#pragma unroll
    for (int f = 0; f < NF; f++) { oA[f] = sB2[f]; oB[f] = sB2[f]; }
#pragma unroll
    for (int j = 0; j < HID; j++) {
        float rA = fmaxf(hA[j], 0.f);
        float rB = fmaxf(hB[j], 0.f);
        const float4* wr = reinterpret_cast<const float4*>(&sW2[j * NF]);
        float4 w0 = wr[0], w1 = wr[1];
        oA[0] = fmaf(rA, w0.x, oA[0]); oB[0] = fmaf(rB, w0.x, oB[0]);
        oA[1] = fmaf(rA, w0.y, oA[1]); oB[1] = fmaf(rB, w0.y, oB[1]);
        oA[2] = fmaf(rA, w0.z, oA[2]); oB[2] = fmaf(rB, w0.z, oB[2]);
        oA[3] = fmaf(rA, w0.w, oA[3]); oB[3] = fmaf(rB, w0.w, oB[3]);
        oA[4] = fmaf(rA, w1.x, oA[4]); oB[4] = fmaf(rB, w1.x, oB[4]);
        oA[5] = fmaf(rA, w1.y, oA[5]); oB[5] = fmaf(rB, w1.y, oB[5]);
        oA[6] = fmaf(rA, w1.z, oA[6]); oB[6] = fmaf(rB, w1.z, oB[6]);
        oA[7] = fmaf(rA, w1.w, oA[7]); oB[7] = fmaf(rB, w1.w, oB[7]);
    }

    if (FUSE_U) {
        float4* lnA = reinterpret_cast<float4*>(&d_ln[(size_t)vA * 8]);
        lnA[0] = make_float4(oA[0], oA[1], oA[2], oA[3]);
        lnA[1] = make_float4(oA[4], oA[5], oA[6], oA[7]);
        if (valB) {
            float4* lnB = reinterpret_cast<float4*>(&d_ln[(size_t)vB * 8]);
            lnB[0] = make_float4(oB[0], oB[1], oB[2], oB[3]);
            lnB[1] = make_float4(oB[4], oB[5], oB[6], oB[7]);
        }
        // table build: shared weight loads feed both nodes' accumulators
        float4* dstA = reinterpret_cast<float4*>(&d_hrc_u[(size_t)vA * 64]);
        float4* dstB = reinterpret_cast<float4*>(&d_hrc_u[(size_t)vB * 64]);
#pragma unroll
        for (int half = 0; half < 2; half++) {
            float tA[HID], tB[HID];
#pragma unroll
            for (int j = 0; j < HID; j++) { tA[j] = 0.f; tB[j] = 0.f; }
#pragma unroll
            for (int k = 0; k < 8; k++) {
                float va = oA[k], vb = oB[k];
                const float4* wr = reinterpret_cast<const float4*>(&sUW[(half * 8 + k) * HID]);
#pragma unroll
                for (int j4 = 0; j4 < HID / 4; j4++) {
                    float4 w = wr[j4];
                    tA[j4 * 4 + 0] = fmaf(va, w.x, tA[j4 * 4 + 0]);
                    tB[j4 * 4 + 0] = fmaf(vb, w.x, tB[j4 * 4 + 0]);
                    tA[j4 * 4 + 1] = fmaf(va, w.y, tA[j4 * 4 + 1]);
                    tB[j4 * 4 + 1] = fmaf(vb, w.y, tB[j4 * 4 + 1]);
                    tA[j4 * 4 + 2] = fmaf(va, w.z, tA[j4 * 4 + 2]);
                    tB[j4 * 4 + 2] = fmaf(vb, w.z, tB[j4 * 4 + 2]);
                    tA[j4 * 4 + 3] = fmaf(va, w.w, tA[j4 * 4 + 3]);
                    tB[j4 * 4 + 3] = fmaf(vb, w.w, tB[j4 * 4 + 3]);
                }
            }
#pragma unroll
            for (int j4 = 0; j4 < HID / 4; j4++) {
                dstA[half * 8 + j4] = make_float4(tA[j4 * 4], tA[j4 * 4 + 1], tA[j4 * 4 + 2], tA[j4 * 4 + 3]);
                if (valB)
                    dstB[half * 8 + j4] = make_float4(tB[j4 * 4], tB[j4 * 4 + 1], tB[j4 * 4 + 2], tB[j4 * 4 + 3]);
            }
        }
    }

    // ---- block nsum reduce (both nodes) + fused global update ----
#pragma unroll
    for (int f = 0; f < NF; f++) {
        float contrib = oA[f] + (valB ? oB[f] : 0.f);
        float s = warpAllSum(contrib);
        if ((tid & 31) == 0) sred[tid >> 5][f] = s;
    }
    __syncthreads();
    if (tid < NF) {
        float s = sred[0][tid] + sred[1][tid] + sred[2][tid] + sred[3][tid];
        atomicAdd(&d_nsum[tid], s);
    }

    __syncthreads();
    if (tid == 0) {
        __threadfence();
        unsigned old = atomicAdd(&d_ncnt, 1u);
        s_last = (old == gridDim.x - 1) ? 1 : 0;
    }
    __syncthreads();
    if (s_last && tid < 32) {
        int j = tid;
        float in[17];
#pragma unroll
        for (int f = 0; f < NF; f++) in[f] = __ldcg(&d_nsum[f]) / (float)N_NODES;
        in[8] = __ldcg(&d_esum) / (float)E_EDGES;
#pragma unroll
        for (int f = 0; f < GF; f++) in[9 + f] = __ldcg(&d_g[f]);

        float h = gB1[j];
#pragma unroll
        for (int k = 0; k < 17; k++) h = fmaf(in[k], gW1[k * HID + j], h);
        h = fmaxf(h, 0.f);

        float gnew[GF];
#pragma unroll
        for (int f = 0; f < GF; f++) gnew[f] = __ldg(&gB2[f]) + warpAllSum(h * gW2[j * NF + f]);

        float be = neB1[j], bn = nnB1[j];
#pragma unroll
        for (int f = 0; f < GF; f++) {
            be = fmaf(gnew[f], neW1[f * HID + j], be);
            bn = fmaf(gnew[f], nnW1[f * HID + j], bn);
        }
        d_hbase_e[j] = be;
        d_hbase_n[j] = bn;

        if (j < GF) {
            d_g[j] = gnew[j];
            d_nsum[j] = 0.f;
        }
        if (j == 0) {
            d_esum = 0.f;
            d_ncnt = 0u;
        }
    }
}

// ---------------- host launch ----------------
extern "C" void kernel_launch(void* const* d_in, const int* in_sizes, int n_in,
                              void* d_out, int out_size) {
    const float* x = (const float*)d_in[0];
    const int* lei = (const int*)d_in[1];
    const int* uei = (const int*)d_in[2];
    const float* lattr = (const float*)d_in[3];
    const float* uattr = (const float*)d_in[4];
    const float* eW1 = (const float*)d_in[5];
    const float* eb1 = (const float*)d_in[6];
    const float* eW2 = (const float*)d_in[7];
    const float* eb2 = (const float*)d_in[8];
    const float* nW1 = (const float*)d_in[9];
    const float* nb1 = (const float*)d_in[10];
    const float* nW2 = (const float*)d_in[11];
    const float* nb2 = (const float*)d_in[12];
    const float* gW1 = (const float*)d_in[13];
    const float* gb1 = (const float*)d_in[14];
    const float* gW2 = (const float*)d_in[15];
    const float* gb2 = (const float*)d_in[16];
    float* outp = (float*)d_out;

    const int* lrow = lei;
    const int* lcol = lei + E_EDGES;
    const int* urow = uei;
    const int* ucol = uei + E_EDGES;

    float *p_le, *p_ue, *p_ln, *p_cntl, *p_cntu, *p_hl0, *p_hl1, *p_hl2, *p_hu;
    cudaGetSymbolAddress((void**)&p_le, d_le);
    cudaGetSymbolAddress((void**)&p_ue, d_ue);
    cudaGetSymbolAddress((void**)&p_ln, d_ln);
    cudaGetSymbolAddress((void**)&p_cntl, d_cntl);
    cudaGetSymbolAddress((void**)&p_cntu, d_cntu);
    cudaGetSymbolAddress((void**)&p_hl0, d_hrc_l0);
    cudaGetSymbolAddress((void**)&p_hl1, d_hrc_l1);
    cudaGetSymbolAddress((void**)&p_hl2, d_hrc_l2);
    cudaGetSymbolAddress((void**)&p_hu, d_hrc_u);
    float* p_hl[3] = {p_hl0, p_hl1, p_hl2};

    const int EGB = 1184;

#define EW1P(b, i) (eW1 + (size_t)((b)*3 + (i)) * 26 * HID)
#define EB1P(b, i) (eb1 + ((b)*3 + (i)) * HID)
#define EW2P(b, i) (eW2 + ((b)*3 + (i)) * HID)
#define EB2P(b, i) (eb2 + ((b)*3 + (i)))
#define NW1P(b, i) (nW1 + (size_t)((b)*3 + (i)) * 17 * HID)
#define NB1P(b, i) (nb1 + ((b)*3 + (i)) * HID)
#define NW2P(b, i) (nW2 + (size_t)((b)*3 + (i)) * HID * NF)
#define NB2P(b, i) (nb2 + ((b)*3 + (i)) * NF)
#define GWP(b, i) gW1 + (size_t)((b)*3 + (i)) * 17 * HID, gb1 + ((b)*3 + (i)) * HID, \
                  gW2 + (size_t)((b)*3 + (i)) * HID * NF, gb2 + ((b)*3 + (i)) * NF

    k_zero<<<NPB, 256>>>(EB1P(0, 0), NB1P(0, 0));
    k_setup<<<EBC + 3 * NPB, 256>>>(lrow, urow, x, EW1P(0, 0), EW1P(0, 1), EW1P(0, 2));

    for (int i = 0; i < 3; i++) {
        const float* le_prev = (i == 0) ? lattr : p_le;
        const float* ue_prev = (i == 0) ? uattr : p_ue;
        bool last = (i == 2);

        if (i == 0)
            k_edge<false, false, true><<<EGB, 256>>>(lrow, lcol, le_prev, lattr, EW1P(0, i), EW2P(0, i), EB2P(0, i), p_hl[i], p_le, outp);
        else if (!last)
            k_edge<true, false, true><<<EGB, 256>>>(lrow, lcol, le_prev, lattr, EW1P(0, i), EW2P(0, i), EB2P(0, i), p_hl[i], p_le, outp);
        else
            k_edge<true, true, true><<<EGB, 256>>>(lrow, lcol, le_prev, lattr, EW1P(0, i), EW2P(0, i), EB2P(0, i), p_hl[i], p_le, outp);

        k_node<true><<<NHB, 128>>>(x, p_cntl, NW1P(0, i), NW2P(0, i), NB2P(0, i), EW1P(1, i),
                                   GWP(0, i), EW1P(1, i), EB1P(1, i), NW1P(1, i), NB1P(1, i));

        if (!last)
            k_edge<false, false, true><<<EGB, 256>>>(urow, ucol, ue_prev, uattr, EW1P(1, i), EW2P(1, i), EB2P(1, i), p_hu, p_ue, outp);
        else
            k_edge<false, true, false><<<EGB, 256>>>(urow, ucol, ue_prev, uattr, EW1P(1, i), EW2P(1, i), EB2P(1, i), p_hu, p_ue,
                                                     outp + E_EDGES);

        if (!last)
            k_node<false><<<NHB, 128>>>(p_ln, p_cntu, NW1P(1, i), NW2P(1, i), NB2P(1, i), EW1P(1, i),
                                        GWP(1, i), EW1P(0, i + 1), EB1P(0, i + 1), NW1P(0, i + 1), NB1P(0, i + 1));
    }

#undef EW1P
#undef EB1P
#undef EW2P
#undef EB2P
#undef NW1P
#undef NB1P
#undef NW2P
#undef NB2P
#undef GWP
}

// round 15
// speedup vs baseline: 1.4440x; 1.0615x over previous
#include <cuda_runtime.h>
#include <math.h>

#define N_NODES 100000
#define E_EDGES 1100000
#define HID 32
#define GF 8
#define NF 8

#define EBC ((E_EDGES + 255) / 256)   // edge-count blocks
#define NPB ((N_NODES + 255) / 256)   // per-node prep blocks (256 thr)
#define NHB 391                        // node blocks: 128 thr, 2 nodes/thread (391*128=50048)
#define NSPLIT 50048                   // second node = v + NSPLIT

// ---------------- persistent device scratch ----------------
__device__ __align__(16) float d_hrc_l0[(size_t)N_NODES * 64];
__device__ __align__(16) float d_hrc_l1[(size_t)N_NODES * 64];
__device__ __align__(16) float d_hrc_l2[(size_t)N_NODES * 64];
__device__ __align__(16) float d_hrc_u[(size_t)N_NODES * 64];
__device__ __align__(16) float d_le[E_EDGES];
__device__ __align__(16) float d_ue[E_EDGES];
__device__ __align__(16) float d_ln[N_NODES * NF];
__device__ float d_agg[N_NODES];
__device__ float d_cntl[N_NODES];
__device__ float d_cntu[N_NODES];
__device__ float d_g[GF];
__device__ float d_nsum[GF];
__device__ float d_esum;
__device__ float d_hbase_e[HID];
__device__ float d_hbase_n[HID];
__device__ unsigned d_ncnt;

__inline__ __device__ float warpAllSum(float v) {
#pragma unroll
    for (int o = 16; o > 0; o >>= 1) v += __shfl_xor_sync(0xffffffffu, v, o);
    return v;
}

__inline__ __device__ void l2_prefetch(const void* p) {
    asm volatile("prefetch.global.L2 [%0];" :: "l"(p));
}

// ---------------- init ----------------
__global__ void k_zero(const float* __restrict__ eb1_0, const float* __restrict__ nb1_0) {
    int i = blockIdx.x * blockDim.x + threadIdx.x;
    if (i < N_NODES) {
        d_agg[i] = 0.f;
        d_cntl[i] = 0.f;
        d_cntu[i] = 0.f;
    }
    if (blockIdx.x == 0) {
        int j = threadIdx.x;
        if (j < HID) {
            d_hbase_e[j] = eb1_0[j];
            d_hbase_n[j] = nb1_0[j];
        }
        if (j < GF) { d_g[j] = 0.f; d_nsum[j] = 0.f; }
        if (j == 0) { d_esum = 0.f; d_ncnt = 0u; }
    }
}

// ---------------- prep body: hr = x @ W1[8:16], hc = x @ W1[16:24] ----------------
__device__ __forceinline__ void prep_body(int pb, int tid, float* sW,
                                          const float* __restrict__ xn,
                                          const float* __restrict__ W1,
                                          float* __restrict__ hrc) {
    for (int i = tid; i < 16 * HID; i += 256) sW[i] = W1[8 * HID + i];
    __syncthreads();

    int v = pb * 256 + tid;
    if (v >= N_NODES) return;
    const float4* xp = reinterpret_cast<const float4*>(xn + (size_t)v * 8);
    float4 x0 = xp[0], x1 = xp[1];
    float xv[8] = {x0.x, x0.y, x0.z, x0.w, x1.x, x1.y, x1.z, x1.w};

    float h[HID];
    float4* dst = reinterpret_cast<float4*>(hrc + (size_t)v * 64);
#pragma unroll
    for (int half = 0; half < 2; half++) {
#pragma unroll
        for (int j = 0; j < HID; j++) h[j] = 0.f;
#pragma unroll
        for (int k = 0; k < 8; k++) {
            float val = xv[k];
            const float4* wr = reinterpret_cast<const float4*>(&sW[(half * 8 + k) * HID]);
#pragma unroll
            for (int j4 = 0; j4 < HID / 4; j4++) {
                float4 w = wr[j4];
                h[j4 * 4 + 0] = fmaf(val, w.x, h[j4 * 4 + 0]);
                h[j4 * 4 + 1] = fmaf(val, w.y, h[j4 * 4 + 1]);
                h[j4 * 4 + 2] = fmaf(val, w.z, h[j4 * 4 + 2]);
                h[j4 * 4 + 3] = fmaf(val, w.w, h[j4 * 4 + 3]);
            }
        }
#pragma unroll
        for (int j4 = 0; j4 < HID / 4; j4++)
            dst[half * 8 + j4] = make_float4(h[j4 * 4], h[j4 * 4 + 1], h[j4 * 4 + 2], h[j4 * 4 + 3]);
    }
}

// ---------------- setup mega-kernel ----------------
__global__ __launch_bounds__(256) void k_setup(const int* __restrict__ lrow,
                                               const int* __restrict__ urow,
                                               const float* __restrict__ x,
                                               const float* __restrict__ eW1_0,
                                               const float* __restrict__ eW1_1,
                                               const float* __restrict__ eW1_2) {
    __shared__ __align__(16) float sW[16 * HID];
    int bid = blockIdx.x;
    int tid = threadIdx.x;
    if (bid < EBC) {
        int e = bid * 256 + tid;
        if (e < E_EDGES) {
            atomicAdd(&d_cntl[lrow[e]], 1.0f);
            atomicAdd(&d_cntu[urow[e]], 1.0f);
        }
    } else {
        int t = bid - EBC;
        int layer = t / NPB;
        int pb = t % NPB;
        const float* W1 = (layer == 0) ? eW1_0 : (layer == 1) ? eW1_1 : eW1_2;
        float* hrc = (layer == 0) ? d_hrc_l0 : (layer == 1) ? d_hrc_l1 : d_hrc_l2;
        prep_body(pb, tid, sW, x, W1, hrc);
    }
}

// ---------------- edge kernel: 8 lanes/edge, 4 edges per group-iteration ----------------
template <bool HAS_SKIP, bool WRITE_OUT, bool DO_AGG>
__global__ __launch_bounds__(256) void k_edge(
    const int* __restrict__ row, const int* __restrict__ col,
    const float* __restrict__ eprev, const float* __restrict__ eskip,
    const float* __restrict__ W1,   // 26x32 (rows 24,25 used)
    const float* __restrict__ W2,   // 32
    const float* __restrict__ B2,   // 1
    const float* __restrict__ hrc,  // N x 64 table
    float* __restrict__ ebuf,
    float* __restrict__ outp) {
    __shared__ float sred[8];
    int tid = threadIdx.x;
    int c = tid & 7;
    int g = tid >> 3;

    float base[4], w24[4], w25[4], w2[4];
#pragma unroll
    for (int i = 0; i < 4; i++) {
        base[i] = d_hbase_e[c * 4 + i];
        w24[i] = __ldg(&W1[24 * HID + c * 4 + i]);
        w25[i] = HAS_SKIP ? __ldg(&W1[25 * HID + c * 4 + i]) : 0.f;
        w2[i] = __ldg(&W2[c * 4 + i]);
    }
    float b2 = __ldg(B2);

    float esum_local = 0.f;
    const int step = gridDim.x * 128;
    for (int e0 = (blockIdx.x * 32 + g) * 4; e0 < E_EDGES; e0 += step) {
        int4 rr = *reinterpret_cast<const int4*>(&row[e0]);
        int4 cc = *reinterpret_cast<const int4*>(&col[e0]);
        float4 epv = *reinterpret_cast<const float4*>(&eprev[e0]);
        float4 esv = HAS_SKIP ? *reinterpret_cast<const float4*>(&eskip[e0])
                              : make_float4(0.f, 0.f, 0.f, 0.f);
        int r[4] = {rr.x, rr.y, rr.z, rr.w};
        int cl[4] = {cc.x, cc.y, cc.z, cc.w};
        float ep[4] = {epv.x, epv.y, epv.z, epv.w};
        float es[4] = {esv.x, esv.y, esv.z, esv.w};

        float4 hr[4], hc[4];
#pragma unroll
        for (int i = 0; i < 4; i++) {
            hr[i] = *reinterpret_cast<const float4*>(&hrc[(unsigned)r[i] * 64 + c * 4]);
            hc[i] = *reinterpret_cast<const float4*>(&hrc[(unsigned)cl[i] * 64 + 32 + c * 4]);
        }

        float p[4];
#pragma unroll
        for (int i = 0; i < 4; i++) {
            float t, q = 0.f;
            t = base[0] + hr[i].x + hc[i].x; t = fmaf(ep[i], w24[0], t); if (HAS_SKIP) t = fmaf(es[i], w25[0], t);
            q = fmaf(fmaxf(t, 0.f), w2[0], q);
            t = base[1] + hr[i].y + hc[i].y; t = fmaf(ep[i], w24[1], t); if (HAS_SKIP) t = fmaf(es[i], w25[1], t);
            q = fmaf(fmaxf(t, 0.f), w2[1], q);
            t = base[2] + hr[i].z + hc[i].z; t = fmaf(ep[i], w24[2], t); if (HAS_SKIP) t = fmaf(es[i], w25[2], t);
            q = fmaf(fmaxf(t, 0.f), w2[2], q);
            t = base[3] + hr[i].w + hc[i].w; t = fmaf(ep[i], w24[3], t); if (HAS_SKIP) t = fmaf(es[i], w25[3], t);
            q = fmaf(fmaxf(t, 0.f), w2[3], q);
            p[i] = q;
        }

#pragma unroll
        for (int i = 0; i < 4; i++) p[i] += __shfl_down_sync(0xffffffffu, p[i], 4);
#pragma unroll
        for (int i = 0; i < 4; i++) p[i] += __shfl_down_sync(0xffffffffu, p[i], 2);
#pragma unroll
        for (int i = 0; i < 4; i++) p[i] += __shfl_down_sync(0xffffffffu, p[i], 1);

        if (c == 0) {
            float o[4];
#pragma unroll
            for (int i = 0; i < 4; i++) o[i] = p[i] + b2;
            *reinterpret_cast<float4*>(&ebuf[e0]) = make_float4(o[0], o[1], o[2], o[3]);
            if (DO_AGG) {
#pragma unroll
                for (int i = 0; i < 4; i++) {
                    atomicAdd(&d_agg[r[i]], o[i]);
                    esum_local += o[i];
                }
            }
            if (WRITE_OUT) {
                float q[4];
#pragma unroll
                for (int i = 0; i < 4; i++) q[i] = (r[i] == cl[i]) ? expf(o[i]) : o[i];
                *reinterpret_cast<float4*>(&outp[e0]) = make_float4(q[0], q[1], q[2], q[3]);
            }
        }
    }

    if (DO_AGG) {
        float s = warpAllSum(esum_local);
        if ((tid & 31) == 0) sred[tid >> 5] = s;
        __syncthreads();
        if (tid < 8) {
            float v = sred[tid];
            v += __shfl_xor_sync(0xffu, v, 1);
            v += __shfl_xor_sync(0xffu, v, 2);
            v += __shfl_xor_sync(0xffu, v, 4);
            if (tid == 0) atomicAdd(&d_esum, v);
        }
    }
}

// ---------------- node kernel: 128 thr, 2 nodes/thread, register-chunked ----------------
template <bool FUSE_U>
__global__ __launch_bounds__(128, 4) void k_node(
    const float* __restrict__ xn,   // N x 8 (x or ln)
    const float* __restrict__ cnt,  // N
    const float* __restrict__ W1,   // 17 x 32 (rows 8..16 used)
    const float* __restrict__ W2,   // 32 x 8
    const float* __restrict__ B2,   // 8
    const float* __restrict__ uW1,  // next (upper) edge W1, rows 8..24 (FUSE_U)
    const float* __restrict__ gW1, const float* __restrict__ gB1,
    const float* __restrict__ gW2, const float* __restrict__ gB2,
    const float* __restrict__ neW1, const float* __restrict__ neB1,
    const float* __restrict__ nnW1, const float* __restrict__ nnB1) {
    __shared__ __align__(16) float sW1[9 * HID];
    __shared__ __align__(16) float sW2[HID * NF];
    __shared__ __align__(16) float sUW[16 * HID];
    __shared__ float sB2[NF];
    __shared__ float sbase[HID];
    __shared__ float sred[4][NF];
    __shared__ int s_last;

    int tid = threadIdx.x;
    for (int i = tid; i < 9 * HID; i += 128) sW1[i] = W1[8 * HID + i];
    for (int i = tid; i < HID * NF; i += 128) sW2[i] = W2[i];
    if (FUSE_U)
        for (int i = tid; i < 16 * HID; i += 128) sUW[i] = uW1[8 * HID + i];
    if (tid < HID) sbase[tid] = d_hbase_n[tid];
    if (tid < NF) sB2[tid] = B2[tid];
    // warm L2 for the fused-global tail
    if (tid < 17) l2_prefetch(gW1 + tid * 32);
    else if (tid < 25) l2_prefetch(gW2 + (tid - 17) * 32);
    else if (tid < 33) l2_prefetch(neW1 + (tid - 25) * 32);
    else if (tid < 41) l2_prefetch(nnW1 + (tid - 33) * 32);
    else if (tid == 41) l2_prefetch(gB1);
    else if (tid == 42) l2_prefetch(neB1);
    else if (tid == 43) l2_prefetch(nnB1);
    else if (tid == 44) l2_prefetch(gB2);
    __syncthreads();

    int vA = blockIdx.x * 128 + tid;   // always < NSPLIT <= N_NODES
    int vB = vA + NSPLIT;
    bool valB = (vB < N_NODES);

    // ---- inputs for both nodes ----
    const float4* xpA = reinterpret_cast<const float4*>(xn + (size_t)vA * 8);
    float4 xA0 = xpA[0], xA1 = xpA[1];
    float aA = d_agg[vA] / fmaxf(cnt[vA], 1.0f);
    d_agg[vA] = 0.f;
    float4 xB0 = make_float4(0.f, 0.f, 0.f, 0.f), xB1 = xB0;
    float aB = 0.f;
    if (valB) {
        const float4* xpB = reinterpret_cast<const float4*>(xn + (size_t)vB * 8);
        xB0 = xpB[0]; xB1 = xpB[1];
        aB = d_agg[vB] / fmaxf(cnt[vB], 1.0f);
        d_agg[vB] = 0.f;
    }
    float xvA[8] = {xA0.x, xA0.y, xA0.z, xA0.w, xA1.x, xA1.y, xA1.z, xA1.w};
    float xvB[8] = {xB0.x, xB0.y, xB0.z, xB0.w, xB1.x, xB1.y, xB1.z, xB1.w};

    // ---- layers 1+2 in two 16-unit halves (bounds live h regs to 32) ----
    float oA[NF], oB[NF];
#pragma unroll
    for (int f = 0; f < NF; f++) { oA[f] = sB2[f]; oB[f] = sB2[f]; }
#pragma unroll
    for (int half = 0; half < 2; half++) {
        float hA[16], hB[16];
#pragma unroll
        for (int m = 0; m < 16; m++) {
            float b = sbase[half * 16 + m];
            hA[m] = b; hB[m] = b;
        }
#pragma unroll
        for (int k = 0; k < 9; k++) {
            float va = (k < 8) ? xvA[k] : aA;
            float vb = (k < 8) ? xvB[k] : aB;
            const float4* wr = reinterpret_cast<const float4*>(&sW1[k * HID + half * 16]);
#pragma unroll
            for (int m4 = 0; m4 < 4; m4++) {
                float4 w = wr[m4];
                hA[m4 * 4 + 0] = fmaf(va, w.x, hA[m4 * 4 + 0]);
                hB[m4 * 4 + 0] = fmaf(vb, w.x, hB[m4 * 4 + 0]);
                hA[m4 * 4 + 1] = fmaf(va, w.y, hA[m4 * 4 + 1]);
                hB[m4 * 4 + 1] = fmaf(vb, w.y, hB[m4 * 4 + 1]);
                hA[m4 * 4 + 2] = fmaf(va, w.z, hA[m4 * 4 + 2]);
                hB[m4 * 4 + 2] = fmaf(vb, w.z, hB[m4 * 4 + 2]);
                hA[m4 * 4 + 3] = fmaf(va, w.w, hA[m4 * 4 + 3]);
                hB[m4 * 4 + 3] = fmaf(vb, w.w, hB[m4 * 4 + 3]);
            }
        }
#pragma unroll
        for (int jj = 0; jj < 16; jj++) {
            float rA = fmaxf(hA[jj], 0.f);
            float rB = fmaxf(hB[jj], 0.f);
            const float4* wr = reinterpret_cast<const float4*>(&sW2[(half * 16 + jj) * NF]);
            float4 w0 = wr[0], w1 = wr[1];
            oA[0] = fmaf(rA, w0.x, oA[0]); oB[0] = fmaf(rB, w0.x, oB[0]);
            oA[1] = fmaf(rA, w0.y, oA[1]); oB[1] = fmaf(rB, w0.y, oB[1]);
            oA[2] = fmaf(rA, w0.z, oA[2]); oB[2] = fmaf(rB, w0.z, oB[2]);
            oA[3] = fmaf(rA, w0.w, oA[3]); oB[3] = fmaf(rB, w0.w, oB[3]);
            oA[4] = fmaf(rA, w1.x, oA[4]); oB[4] = fmaf(rB, w1.x, oB[4]);
            oA[5] = fmaf(rA, w1.y, oA[5]); oB[5] = fmaf(rB, w1.y, oB[5]);
            oA[6] = fmaf(rA, w1.z, oA[6]); oB[6] = fmaf(rB, w1.z, oB[6]);
            oA[7] = fmaf(rA, w1.w, oA[7]); oB[7] = fmaf(rB, w1.w, oB[7]);
        }
    }

    if (FUSE_U) {
        float4* lnA = reinterpret_cast<float4*>(&d_ln[(size_t)vA * 8]);
        lnA[0] = make_float4(oA[0], oA[1], oA[2], oA[3]);
        lnA[1] = make_float4(oA[4], oA[5], oA[6], oA[7]);
        if (valB) {
            float4* lnB = reinterpret_cast<float4*>(&d_ln[(size_t)vB * 8]);
            lnB[0] = make_float4(oB[0], oB[1], oB[2], oB[3]);
            lnB[1] = make_float4(oB[4], oB[5], oB[6], oB[7]);
        }
        // table build in four 16-col chunks (bounds live t regs to 32)
        float4* dstA = reinterpret_cast<float4*>(&d_hrc_u[(size_t)vA * 64]);
        float4* dstB = reinterpret_cast<float4*>(&d_hrc_u[(size_t)vB * 64]);
#pragma unroll
        for (int half = 0; half < 2; half++) {
#pragma unroll
            for (int cnk = 0; cnk < 2; cnk++) {
                float tA[16], tB[16];
#pragma unroll
                for (int m = 0; m < 16; m++) { tA[m] = 0.f; tB[m] = 0.f; }
#pragma unroll
                for (int k = 0; k < 8; k++) {
                    float va = oA[k], vb = oB[k];
                    const float4* wr = reinterpret_cast<const float4*>(&sUW[(half * 8 + k) * HID + cnk * 16]);
#pragma unroll
                    for (int m4 = 0; m4 < 4; m4++) {
                        float4 w = wr[m4];
                        tA[m4 * 4 + 0] = fmaf(va, w.x, tA[m4 * 4 + 0]);
                        tB[m4 * 4 + 0] = fmaf(vb, w.x, tB[m4 * 4 + 0]);
                        tA[m4 * 4 + 1] = fmaf(va, w.y, tA[m4 * 4 + 1]);
                        tB[m4 * 4 + 1] = fmaf(vb, w.y, tB[m4 * 4 + 1]);
                        tA[m4 * 4 + 2] = fmaf(va, w.z, tA[m4 * 4 + 2]);
                        tB[m4 * 4 + 2] = fmaf(vb, w.z, tB[m4 * 4 + 2]);
                        tA[m4 * 4 + 3] = fmaf(va, w.w, tA[m4 * 4 + 3]);
                        tB[m4 * 4 + 3] = fmaf(vb, w.w, tB[m4 * 4 + 3]);
                    }
                }
#pragma unroll
                for (int m4 = 0; m4 < 4; m4++) {
                    dstA[half * 8 + cnk * 4 + m4] = make_float4(tA[m4 * 4], tA[m4 * 4 + 1], tA[m4 * 4 + 2], tA[m4 * 4 + 3]);
                    if (valB)
                        dstB[half * 8 + cnk * 4 + m4] = make_float4(tB[m4 * 4], tB[m4 * 4 + 1], tB[m4 * 4 + 2], tB[m4 * 4 + 3]);
                }
            }
        }
    }

    // ---- block nsum reduce (both nodes) + fused global update ----
#pragma unroll
    for (int f = 0; f < NF; f++) {
        float contrib = oA[f] + (valB ? oB[f] : 0.f);
        float s = warpAllSum(contrib);
        if ((tid & 31) == 0) sred[tid >> 5][f] = s;
    }
    __syncthreads();
    if (tid < NF) {
        float s = sred[0][tid] + sred[1][tid] + sred[2][tid] + sred[3][tid];
        atomicAdd(&d_nsum[tid], s);
    }

    __syncthreads();
    if (tid == 0) {
        __threadfence();
        unsigned old = atomicAdd(&d_ncnt, 1u);
        s_last = (old == gridDim.x - 1) ? 1 : 0;
    }
    __syncthreads();
    if (s_last && tid < 32) {
        int j = tid;
        float in[17];
#pragma unroll
        for (int f = 0; f < NF; f++) in[f] = __ldcg(&d_nsum[f]) / (float)N_NODES;
        in[8] = __ldcg(&d_esum) / (float)E_EDGES;
#pragma unroll
        for (int f = 0; f < GF; f++) in[9 + f] = __ldcg(&d_g[f]);

        float h = gB1[j];
#pragma unroll
        for (int k = 0; k < 17; k++) h = fmaf(in[k], gW1[k * HID + j], h);
        h = fmaxf(h, 0.f);

        float gnew[GF];
#pragma unroll
        for (int f = 0; f < GF; f++) gnew[f] = __ldg(&gB2[f]) + warpAllSum(h * gW2[j * NF + f]);

        float be = neB1[j], bn = nnB1[j];
#pragma unroll
        for (int f = 0; f < GF; f++) {
            be = fmaf(gnew[f], neW1[f * HID + j], be);
            bn = fmaf(gnew[f], nnW1[f * HID + j], bn);
        }
        d_hbase_e[j] = be;
        d_hbase_n[j] = bn;

        if (j < GF) {
            d_g[j] = gnew[j];
            d_nsum[j] = 0.f;
        }
        if (j == 0) {
            d_esum = 0.f;
            d_ncnt = 0u;
        }
    }
}

// ---------------- host launch ----------------
extern "C" void kernel_launch(void* const* d_in, const int* in_sizes, int n_in,
                              void* d_out, int out_size) {
    const float* x = (const float*)d_in[0];
    const int* lei = (const int*)d_in[1];
    const int* uei = (const int*)d_in[2];
    const float* lattr = (const float*)d_in[3];
    const float* uattr = (const float*)d_in[4];
    const float* eW1 = (const float*)d_in[5];
    const float* eb1 = (const float*)d_in[6];
    const float* eW2 = (const float*)d_in[7];
    const float* eb2 = (const float*)d_in[8];
    const float* nW1 = (const float*)d_in[9];
    const float* nb1 = (const float*)d_in[10];
    const float* nW2 = (const float*)d_in[11];
    const float* nb2 = (const float*)d_in[12];
    const float* gW1 = (const float*)d_in[13];
    const float* gb1 = (const float*)d_in[14];
    const float* gW2 = (const float*)d_in[15];
    const float* gb2 = (const float*)d_in[16];
    float* outp = (float*)d_out;

    const int* lrow = lei;
    const int* lcol = lei + E_EDGES;
    const int* urow = uei;
    const int* ucol = uei + E_EDGES;

    float *p_le, *p_ue, *p_ln, *p_cntl, *p_cntu, *p_hl0, *p_hl1, *p_hl2, *p_hu;
    cudaGetSymbolAddress((void**)&p_le, d_le);
    cudaGetSymbolAddress((void**)&p_ue, d_ue);
    cudaGetSymbolAddress((void**)&p_ln, d_ln);
    cudaGetSymbolAddress((void**)&p_cntl, d_cntl);
    cudaGetSymbolAddress((void**)&p_cntu, d_cntu);
    cudaGetSymbolAddress((void**)&p_hl0, d_hrc_l0);
    cudaGetSymbolAddress((void**)&p_hl1, d_hrc_l1);
    cudaGetSymbolAddress((void**)&p_hl2, d_hrc_l2);
    cudaGetSymbolAddress((void**)&p_hu, d_hrc_u);
    float* p_hl[3] = {p_hl0, p_hl1, p_hl2};

    const int EGB = 1184;

#define EW1P(b, i) (eW1 + (size_t)((b)*3 + (i)) * 26 * HID)
#define EB1P(b, i) (eb1 + ((b)*3 + (i)) * HID)
#define EW2P(b, i) (eW2 + ((b)*3 + (i)) * HID)
#define EB2P(b, i) (eb2 + ((b)*3 + (i)))
#define NW1P(b, i) (nW1 + (size_t)((b)*3 + (i)) * 17 * HID)
#define NB1P(b, i) (nb1 + ((b)*3 + (i)) * HID)
#define NW2P(b, i) (nW2 + (size_t)((b)*3 + (i)) * HID * NF)
#define NB2P(b, i) (nb2 + ((b)*3 + (i)) * NF)
#define GWP(b, i) gW1 + (size_t)((b)*3 + (i)) * 17 * HID, gb1 + ((b)*3 + (i)) * HID, \
                  gW2 + (size_t)((b)*3 + (i)) * HID * NF, gb2 + ((b)*3 + (i)) * NF

    k_zero<<<NPB, 256>>>(EB1P(0, 0), NB1P(0, 0));
    k_setup<<<EBC + 3 * NPB, 256>>>(lrow, urow, x, EW1P(0, 0), EW1P(0, 1), EW1P(0, 2));

    for (int i = 0; i < 3; i++) {
        const float* le_prev = (i == 0) ? lattr : p_le;
        const float* ue_prev = (i == 0) ? uattr : p_ue;
        bool last = (i == 2);

        if (i == 0)
            k_edge<false, false, true><<<EGB, 256>>>(lrow, lcol, le_prev, lattr, EW1P(0, i), EW2P(0, i), EB2P(0, i), p_hl[i], p_le, outp);
        else if (!last)
            k_edge<true, false, true><<<EGB, 256>>>(lrow, lcol, le_prev, lattr, EW1P(0, i), EW2P(0, i), EB2P(0, i), p_hl[i], p_le, outp);
        else
            k_edge<true, true, true><<<EGB, 256>>>(lrow, lcol, le_prev, lattr, EW1P(0, i), EW2P(0, i), EB2P(0, i), p_hl[i], p_le, outp);

        k_node<true><<<NHB, 128>>>(x, p_cntl, NW1P(0, i), NW2P(0, i), NB2P(0, i), EW1P(1, i),
                                   GWP(0, i), EW1P(1, i), EB1P(1, i), NW1P(1, i), NB1P(1, i));

        if (!last)
            k_edge<false, false, true><<<EGB, 256>>>(urow, ucol, ue_prev, uattr, EW1P(1, i), EW2P(1, i), EB2P(1, i), p_hu, p_ue, outp);
        else
            k_edge<false, true, false><<<EGB, 256>>>(urow, ucol, ue_prev, uattr, EW1P(1, i), EW2P(1, i), EB2P(1, i), p_hu, p_ue,
                                                     outp + E_EDGES);

        if (!last)
            k_node<false><<<NHB, 128>>>(p_ln, p_cntu, NW1P(1, i), NW2P(1, i), NB2P(1, i), EW1P(1, i),
                                        GWP(1, i), EW1P(0, i + 1), EB1P(0, i + 1), NW1P(0, i + 1), NB1P(0, i + 1));
    }

#undef EW1P
#undef EB1P
#undef EW2P
#undef EB2P
#undef NW1P
#undef NB1P
#undef NW2P
#undef NB2P
#undef GWP
}

// round 16
// speedup vs baseline: 1.4544x; 1.0072x over previous
#include <cuda_runtime.h>
#include <math.h>

#define N_NODES 100000
#define E_EDGES 1100000
#define HID 32
#define GF 8
#define NF 8

#define EBC ((E_EDGES + 255) / 256)   // edge-count blocks
#define NPB ((N_NODES + 255) / 256)   // per-node prep blocks (256 thr)
#define NHB 391                        // node blocks: 128 thr, 2 nodes/thread (391*128=50048)
#define NSPLIT 50048                   // second node = v + NSPLIT

// ---------------- persistent device scratch ----------------
__device__ __align__(16) float d_hrc_l0[(size_t)N_NODES * 64];
__device__ __align__(16) float d_hrc_l1[(size_t)N_NODES * 64];
__device__ __align__(16) float d_hrc_l2[(size_t)N_NODES * 64];
__device__ __align__(16) float d_hrc_u[(size_t)N_NODES * 64];
__device__ __align__(16) float d_le[E_EDGES];
__device__ __align__(16) float d_ue[E_EDGES];
__device__ __align__(16) float d_ln[N_NODES * NF];
__device__ float d_agg[N_NODES];
__device__ float d_cntl[N_NODES];
__device__ float d_cntu[N_NODES];
__device__ float d_g[GF];
__device__ float d_nsum[GF];
__device__ float d_esum;
__device__ float d_hbase_e[HID];
__device__ float d_hbase_n[HID];
__device__ unsigned d_ncnt;

__inline__ __device__ float warpAllSum(float v) {
#pragma unroll
    for (int o = 16; o > 0; o >>= 1) v += __shfl_xor_sync(0xffffffffu, v, o);
    return v;
}

__inline__ __device__ void l2_prefetch(const void* p) {
    asm volatile("prefetch.global.L2 [%0];" :: "l"(p));
}

// ---------------- init ----------------
__global__ void k_zero(const float* __restrict__ eb1_0, const float* __restrict__ nb1_0) {
    int i = blockIdx.x * blockDim.x + threadIdx.x;
    if (i < N_NODES) {
        d_agg[i] = 0.f;
        d_cntl[i] = 0.f;
        d_cntu[i] = 0.f;
    }
    if (blockIdx.x == 0) {
        int j = threadIdx.x;
        if (j < HID) {
            d_hbase_e[j] = eb1_0[j];
            d_hbase_n[j] = nb1_0[j];
        }
        if (j < GF) { d_g[j] = 0.f; d_nsum[j] = 0.f; }
        if (j == 0) { d_esum = 0.f; d_ncnt = 0u; }
    }
}

// ---------------- prep body: hr = x @ W1[8:16], hc = x @ W1[16:24] ----------------
__device__ __forceinline__ void prep_body(int pb, int tid, float* sW,
                                          const float* __restrict__ xn,
                                          const float* __restrict__ W1,
                                          float* __restrict__ hrc) {
    for (int i = tid; i < 16 * HID; i += 256) sW[i] = W1[8 * HID + i];
    __syncthreads();

    int v = pb * 256 + tid;
    if (v >= N_NODES) return;
    const float4* xp = reinterpret_cast<const float4*>(xn + (size_t)v * 8);
    float4 x0 = xp[0], x1 = xp[1];
    float xv[8] = {x0.x, x0.y, x0.z, x0.w, x1.x, x1.y, x1.z, x1.w};

    float h[HID];
    float4* dst = reinterpret_cast<float4*>(hrc + (size_t)v * 64);
#pragma unroll
    for (int half = 0; half < 2; half++) {
#pragma unroll
        for (int j = 0; j < HID; j++) h[j] = 0.f;
#pragma unroll
        for (int k = 0; k < 8; k++) {
            float val = xv[k];
            const float4* wr = reinterpret_cast<const float4*>(&sW[(half * 8 + k) * HID]);
#pragma unroll
            for (int j4 = 0; j4 < HID / 4; j4++) {
                float4 w = wr[j4];
                h[j4 * 4 + 0] = fmaf(val, w.x, h[j4 * 4 + 0]);
                h[j4 * 4 + 1] = fmaf(val, w.y, h[j4 * 4 + 1]);
                h[j4 * 4 + 2] = fmaf(val, w.z, h[j4 * 4 + 2]);
                h[j4 * 4 + 3] = fmaf(val, w.w, h[j4 * 4 + 3]);
            }
        }
#pragma unroll
        for (int j4 = 0; j4 < HID / 4; j4++)
            dst[half * 8 + j4] = make_float4(h[j4 * 4], h[j4 * 4 + 1], h[j4 * 4 + 2], h[j4 * 4 + 3]);
    }
}

// ---------------- setup mega-kernel ----------------
__global__ __launch_bounds__(256) void k_setup(const int* __restrict__ lrow,
                                               const int* __restrict__ urow,
                                               const float* __restrict__ x,
                                               const float* __restrict__ eW1_0,
                                               const float* __restrict__ eW1_1,
                                               const float* __restrict__ eW1_2) {
    __shared__ __align__(16) float sW[16 * HID];
    int bid = blockIdx.x;
    int tid = threadIdx.x;
    if (bid < EBC) {
        int e = bid * 256 + tid;
        if (e < E_EDGES) {
            atomicAdd(&d_cntl[lrow[e]], 1.0f);
            atomicAdd(&d_cntu[urow[e]], 1.0f);
        }
    } else {
        int t = bid - EBC;
        int layer = t / NPB;
        int pb = t % NPB;
        const float* W1 = (layer == 0) ? eW1_0 : (layer == 1) ? eW1_1 : eW1_2;
        float* hrc = (layer == 0) ? d_hrc_l0 : (layer == 1) ? d_hrc_l1 : d_hrc_l2;
        prep_body(pb, tid, sW, x, W1, hrc);
    }
}

// ---------------- edge kernel: 8 lanes/edge, 4 edges per group-iteration ----------------
template <bool HAS_SKIP, bool WRITE_OUT, bool DO_AGG>
__global__ __launch_bounds__(256) void k_edge(
    const int* __restrict__ row, const int* __restrict__ col,
    const float* __restrict__ eprev, const float* __restrict__ eskip,
    const float* __restrict__ W1,   // 26x32 (rows 24,25 used)
    const float* __restrict__ W2,   // 32
    const float* __restrict__ B2,   // 1
    const float* __restrict__ hrc,  // N x 64 table
    float* __restrict__ ebuf,
    float* __restrict__ outp) {
    __shared__ float sred[8];
    int tid = threadIdx.x;
    int c = tid & 7;
    int g = tid >> 3;

    float base[4], w24[4], w25[4], w2[4];
#pragma unroll
    for (int i = 0; i < 4; i++) {
        base[i] = d_hbase_e[c * 4 + i];
        w24[i] = __ldg(&W1[24 * HID + c * 4 + i]);
        w25[i] = HAS_SKIP ? __ldg(&W1[25 * HID + c * 4 + i]) : 0.f;
        w2[i] = __ldg(&W2[c * 4 + i]);
    }
    float b2 = __ldg(B2);

    float esum_local = 0.f;
    const int step = gridDim.x * 128;
    for (int e0 = (blockIdx.x * 32 + g) * 4; e0 < E_EDGES; e0 += step) {
        int4 rr = *reinterpret_cast<const int4*>(&row[e0]);
        int4 cc = *reinterpret_cast<const int4*>(&col[e0]);
        float4 epv = *reinterpret_cast<const float4*>(&eprev[e0]);
        float4 esv = HAS_SKIP ? *reinterpret_cast<const float4*>(&eskip[e0])
                              : make_float4(0.f, 0.f, 0.f, 0.f);
        int r[4] = {rr.x, rr.y, rr.z, rr.w};
        int cl[4] = {cc.x, cc.y, cc.z, cc.w};
        float ep[4] = {epv.x, epv.y, epv.z, epv.w};
        float es[4] = {esv.x, esv.y, esv.z, esv.w};

        float4 hr[4], hc[4];
#pragma unroll
        for (int i = 0; i < 4; i++) {
            hr[i] = *reinterpret_cast<const float4*>(&hrc[(unsigned)r[i] * 64 + c * 4]);
            hc[i] = *reinterpret_cast<const float4*>(&hrc[(unsigned)cl[i] * 64 + 32 + c * 4]);
        }

        float p[4];
#pragma unroll
        for (int i = 0; i < 4; i++) {
            float t, q = 0.f;
            t = base[0] + hr[i].x + hc[i].x; t = fmaf(ep[i], w24[0], t); if (HAS_SKIP) t = fmaf(es[i], w25[0], t);
            q = fmaf(fmaxf(t, 0.f), w2[0], q);
            t = base[1] + hr[i].y + hc[i].y; t = fmaf(ep[i], w24[1], t); if (HAS_SKIP) t = fmaf(es[i], w25[1], t);
            q = fmaf(fmaxf(t, 0.f), w2[1], q);
            t = base[2] + hr[i].z + hc[i].z; t = fmaf(ep[i], w24[2], t); if (HAS_SKIP) t = fmaf(es[i], w25[2], t);
            q = fmaf(fmaxf(t, 0.f), w2[2], q);
            t = base[3] + hr[i].w + hc[i].w; t = fmaf(ep[i], w24[3], t); if (HAS_SKIP) t = fmaf(es[i], w25[3], t);
            q = fmaf(fmaxf(t, 0.f), w2[3], q);
            p[i] = q;
        }

#pragma unroll
        for (int i = 0; i < 4; i++) p[i] += __shfl_down_sync(0xffffffffu, p[i], 4);
#pragma unroll
        for (int i = 0; i < 4; i++) p[i] += __shfl_down_sync(0xffffffffu, p[i], 2);
#pragma unroll
        for (int i = 0; i < 4; i++) p[i] += __shfl_down_sync(0xffffffffu, p[i], 1);

        if (c == 0) {
            float o[4];
#pragma unroll
            for (int i = 0; i < 4; i++) o[i] = p[i] + b2;
            *reinterpret_cast<float4*>(&ebuf[e0]) = make_float4(o[0], o[1], o[2], o[3]);
            if (DO_AGG) {
#pragma unroll
                for (int i = 0; i < 4; i++) {
                    atomicAdd(&d_agg[r[i]], o[i]);
                    esum_local += o[i];
                }
            }
            if (WRITE_OUT) {
                float q[4];
#pragma unroll
                for (int i = 0; i < 4; i++) q[i] = (r[i] == cl[i]) ? expf(o[i]) : o[i];
                *reinterpret_cast<float4*>(&outp[e0]) = make_float4(q[0], q[1], q[2], q[3]);
            }
        }
    }

    if (DO_AGG) {
        float s = warpAllSum(esum_local);
        if ((tid & 31) == 0) sred[tid >> 5] = s;
        __syncthreads();
        if (tid < 8) {
            float v = sred[tid];
            v += __shfl_xor_sync(0xffu, v, 1);
            v += __shfl_xor_sync(0xffu, v, 2);
            v += __shfl_xor_sync(0xffu, v, 4);
            if (tid == 0) atomicAdd(&d_esum, v);
        }
    }
}

// ---------------- node kernel: 128 thr, 2 nodes/thread, register-chunked ----------------
template <bool FUSE_U>
__global__ __launch_bounds__(128, 4) void k_node(
    const float* __restrict__ xn,   // N x 8 (x or ln)
    const float* __restrict__ cnt,  // N
    const float* __restrict__ W1,   // 17 x 32 (rows 8..16 used)
    const float* __restrict__ W2,   // 32 x 8
    const float* __restrict__ B2,   // 8
    const float* __restrict__ uW1,  // next (upper) edge W1, rows 8..24 (FUSE_U)
    const float* __restrict__ gW1, const float* __restrict__ gB1,
    const float* __restrict__ gW2, const float* __restrict__ gB2,
    const float* __restrict__ neW1, const float* __restrict__ neB1,
    const float* __restrict__ nnW1, const float* __restrict__ nnB1) {
    __shared__ __align__(16) float sW1[9 * HID];
    __shared__ __align__(16) float sW2[HID * NF];
    __shared__ __align__(16) float sUW[16 * HID];
    __shared__ float sB2[NF];
    __shared__ float sbase[HID];
    __shared__ float sred[4][NF];
    __shared__ int s_last;

    int tid = threadIdx.x;
    for (int i = tid; i < 9 * HID; i += 128) sW1[i] = W1[8 * HID + i];
    for (int i = tid; i < HID * NF; i += 128) sW2[i] = W2[i];
    if (FUSE_U)
        for (int i = tid; i < 16 * HID; i += 128) sUW[i] = uW1[8 * HID + i];
    if (tid < HID) sbase[tid] = d_hbase_n[tid];
    if (tid < NF) sB2[tid] = B2[tid];
    // warm L2 for the fused-global tail
    if (tid < 17) l2_prefetch(gW1 + tid * 32);
    else if (tid < 25) l2_prefetch(gW2 + (tid - 17) * 32);
    else if (tid < 33) l2_prefetch(neW1 + (tid - 25) * 32);
    else if (tid < 41) l2_prefetch(nnW1 + (tid - 33) * 32);
    else if (tid == 41) l2_prefetch(gB1);
    else if (tid == 42) l2_prefetch(neB1);
    else if (tid == 43) l2_prefetch(nnB1);
    else if (tid == 44) l2_prefetch(gB2);
    __syncthreads();

    int vA = blockIdx.x * 128 + tid;   // always < NSPLIT <= N_NODES
    int vB = vA + NSPLIT;
    bool valB = (vB < N_NODES);

    // ---- inputs for both nodes ----
    const float4* xpA = reinterpret_cast<const float4*>(xn + (size_t)vA * 8);
    float4 xA0 = xpA[0], xA1 = xpA[1];
    float aA = d_agg[vA] / fmaxf(cnt[vA], 1.0f);
    d_agg[vA] = 0.f;
    float4 xB0 = make_float4(0.f, 0.f, 0.f, 0.f), xB1 = xB0;
    float aB = 0.f;
    if (valB) {
        const float4* xpB = reinterpret_cast<const float4*>(xn + (size_t)vB * 8);
        xB0 = xpB[0]; xB1 = xpB[1];
        aB = d_agg[vB] / fmaxf(cnt[vB], 1.0f);
        d_agg[vB] = 0.f;
    }
    float xvA[8] = {xA0.x, xA0.y, xA0.z, xA0.w, xA1.x, xA1.y, xA1.z, xA1.w};
    float xvB[8] = {xB0.x, xB0.y, xB0.z, xB0.w, xB1.x, xB1.y, xB1.z, xB1.w};

    // ---- layers 1+2 in two 16-unit halves (bounds live h regs to 32) ----
    float oA[NF], oB[NF];
#pragma unroll
    for (int f = 0; f < NF; f++) { oA[f] = sB2[f]; oB[f] = sB2[f]; }
#pragma unroll
    for (int half = 0; half < 2; half++) {
        float hA[16], hB[16];
#pragma unroll
        for (int m = 0; m < 16; m++) {
            float b = sbase[half * 16 + m];
            hA[m] = b; hB[m] = b;
        }
#pragma unroll
        for (int k = 0; k < 9; k++) {
            float va = (k < 8) ? xvA[k] : aA;
            float vb = (k < 8) ? xvB[k] : aB;
            const float4* wr = reinterpret_cast<const float4*>(&sW1[k * HID + half * 16]);
#pragma unroll
            for (int m4 = 0; m4 < 4; m4++) {
                float4 w = wr[m4];
                hA[m4 * 4 + 0] = fmaf(va, w.x, hA[m4 * 4 + 0]);
                hB[m4 * 4 + 0] = fmaf(vb, w.x, hB[m4 * 4 + 0]);
                hA[m4 * 4 + 1] = fmaf(va, w.y, hA[m4 * 4 + 1]);
                hB[m4 * 4 + 1] = fmaf(vb, w.y, hB[m4 * 4 + 1]);
                hA[m4 * 4 + 2] = fmaf(va, w.z, hA[m4 * 4 + 2]);
                hB[m4 * 4 + 2] = fmaf(vb, w.z, hB[m4 * 4 + 2]);
                hA[m4 * 4 + 3] = fmaf(va, w.w, hA[m4 * 4 + 3]);
                hB[m4 * 4 + 3] = fmaf(vb, w.w, hB[m4 * 4 + 3]);
            }
        }
#pragma unroll
        for (int jj = 0; jj < 16; jj++) {
            float rA = fmaxf(hA[jj], 0.f);
            float rB = fmaxf(hB[jj], 0.f);
            const float4* wr = reinterpret_cast<const float4*>(&sW2[(half * 16 + jj) * NF]);
            float4 w0 = wr[0], w1 = wr[1];
            oA[0] = fmaf(rA, w0.x, oA[0]); oB[0] = fmaf(rB, w0.x, oB[0]);
            oA[1] = fmaf(rA, w0.y, oA[1]); oB[1] = fmaf(rB, w0.y, oB[1]);
            oA[2] = fmaf(rA, w0.z, oA[2]); oB[2] = fmaf(rB, w0.z, oB[2]);
            oA[3] = fmaf(rA, w0.w, oA[3]); oB[3] = fmaf(rB, w0.w, oB[3]);
            oA[4] = fmaf(rA, w1.x, oA[4]); oB[4] = fmaf(rB, w1.x, oB[4]);
            oA[5] = fmaf(rA, w1.y, oA[5]); oB[5] = fmaf(rB, w1.y, oB[5]);
            oA[6] = fmaf(rA, w1.z, oA[6]); oB[6] = fmaf(rB, w1.z, oB[6]);
            oA[7] = fmaf(rA, w1.w, oA[7]); oB[7] = fmaf(rB, w1.w, oB[7]);
        }
    }

    if (FUSE_U) {
        float4* lnA = reinterpret_cast<float4*>(&d_ln[(size_t)vA * 8]);
        lnA[0] = make_float4(oA[0], oA[1], oA[2], oA[3]);
        lnA[1] = make_float4(oA[4], oA[5], oA[6], oA[7]);
        if (valB) {
            float4* lnB = reinterpret_cast<float4*>(&d_ln[(size_t)vB * 8]);
            lnB[0] = make_float4(oB[0], oB[1], oB[2], oB[3]);
            lnB[1] = make_float4(oB[4], oB[5], oB[6], oB[7]);
        }
        // table build in four 16-col chunks (bounds live t regs to 32)
        float4* dstA = reinterpret_cast<float4*>(&d_hrc_u[(size_t)vA * 64]);
        float4* dstB = reinterpret_cast<float4*>(&d_hrc_u[(size_t)vB * 64]);
#pragma unroll
        for (int half = 0; half < 2; half++) {
#pragma unroll
            for (int cnk = 0; cnk < 2; cnk++) {
                float tA[16], tB[16];
#pragma unroll
                for (int m = 0; m < 16; m++) { tA[m] = 0.f; tB[m] = 0.f; }
#pragma unroll
                for (int k = 0; k < 8; k++) {
                    float va = oA[k], vb = oB[k];
                    const float4* wr = reinterpret_cast<const float4*>(&sUW[(half * 8 + k) * HID + cnk * 16]);
#pragma unroll
                    for (int m4 = 0; m4 < 4; m4++) {
                        float4 w = wr[m4];
                        tA[m4 * 4 + 0] = fmaf(va, w.x, tA[m4 * 4 + 0]);
                        tB[m4 * 4 + 0] = fmaf(vb, w.x, tB[m4 * 4 + 0]);
                        tA[m4 * 4 + 1] = fmaf(va, w.y, tA[m4 * 4 + 1]);
                        tB[m4 * 4 + 1] = fmaf(vb, w.y, tB[m4 * 4 + 1]);
                        tA[m4 * 4 + 2] = fmaf(va, w.z, tA[m4 * 4 + 2]);
                        tB[m4 * 4 + 2] = fmaf(vb, w.z, tB[m4 * 4 + 2]);
                        tA[m4 * 4 + 3] = fmaf(va, w.w, tA[m4 * 4 + 3]);
                        tB[m4 * 4 + 3] = fmaf(vb, w.w, tB[m4 * 4 + 3]);
                    }
                }
#pragma unroll
                for (int m4 = 0; m4 < 4; m4++) {
                    dstA[half * 8 + cnk * 4 + m4] = make_float4(tA[m4 * 4], tA[m4 * 4 + 1], tA[m4 * 4 + 2], tA[m4 * 4 + 3]);
                    if (valB)
                        dstB[half * 8 + cnk * 4 + m4] = make_float4(tB[m4 * 4], tB[m4 * 4 + 1], tB[m4 * 4 + 2], tB[m4 * 4 + 3]);
                }
            }
        }
    }

    // ---- block nsum reduce (both nodes) + fused global update ----
#pragma unroll
    for (int f = 0; f < NF; f++) {
        float contrib = oA[f] + (valB ? oB[f] : 0.f);
        float s = warpAllSum(contrib);
        if ((tid & 31) == 0) sred[tid >> 5][f] = s;
    }
    __syncthreads();
    if (tid < NF) {
        float s = sred[0][tid] + sred[1][tid] + sred[2][tid] + sred[3][tid];
        atomicAdd(&d_nsum[tid], s);
    }

    __syncthreads();
    if (tid == 0) {
        __threadfence();
        unsigned old = atomicAdd(&d_ncnt, 1u);
        s_last = (old == gridDim.x - 1) ? 1 : 0;
    }
    __syncthreads();
    if (s_last && tid < 32) {
        int j = tid;
        float in[17];
#pragma unroll
        for (int f = 0; f < NF; f++) in[f] = __ldcg(&d_nsum[f]) / (float)N_NODES;
        in[8] = __ldcg(&d_esum) / (float)E_EDGES;
#pragma unroll
        for (int f = 0; f < GF; f++) in[9 + f] = __ldcg(&d_g[f]);

        float h = gB1[j];
#pragma unroll
        for (int k = 0; k < 17; k++) h = fmaf(in[k], gW1[k * HID + j], h);
        h = fmaxf(h, 0.f);

        float gnew[GF];
#pragma unroll
        for (int f = 0; f < GF; f++) gnew[f] = __ldg(&gB2[f]) + warpAllSum(h * gW2[j * NF + f]);

        float be = neB1[j], bn = nnB1[j];
#pragma unroll
        for (int f = 0; f < GF; f++) {
            be = fmaf(gnew[f], neW1[f * HID + j], be);
            bn = fmaf(gnew[f], nnW1[f * HID + j], bn);
        }
        d_hbase_e[j] = be;
        d_hbase_n[j] = bn;

        if (j < GF) {
            d_g[j] = gnew[j];
            d_nsum[j] = 0.f;
        }
        if (j == 0) {
            d_esum = 0.f;
            d_ncnt = 0u;
        }
    }
}

// ---------------- host launch ----------------
extern "C" void kernel_launch(void* const* d_in, const int* in_sizes, int n_in,
                              void* d_out, int out_size) {
    const float* x = (const float*)d_in[0];
    const int* lei = (const int*)d_in[1];
    const int* uei = (const int*)d_in[2];
    const float* lattr = (const float*)d_in[3];
    const float* uattr = (const float*)d_in[4];
    const float* eW1 = (const float*)d_in[5];
    const float* eb1 = (const float*)d_in[6];
    const float* eW2 = (const float*)d_in[7];
    const float* eb2 = (const float*)d_in[8];
    const float* nW1 = (const float*)d_in[9];
    const float* nb1 = (const float*)d_in[10];
    const float* nW2 = (const float*)d_in[11];
    const float* nb2 = (const float*)d_in[12];
    const float* gW1 = (const float*)d_in[13];
    const float* gb1 = (const float*)d_in[14];
    const float* gW2 = (const float*)d_in[15];
    const float* gb2 = (const float*)d_in[16];
    float* outp = (float*)d_out;

    const int* lrow = lei;
    const int* lcol = lei + E_EDGES;
    const int* urow = uei;
    const int* ucol = uei + E_EDGES;

    float *p_le, *p_ue, *p_ln, *p_cntl, *p_cntu, *p_hl0, *p_hl1, *p_hl2, *p_hu;
    cudaGetSymbolAddress((void**)&p_le, d_le);
    cudaGetSymbolAddress((void**)&p_ue, d_ue);
    cudaGetSymbolAddress((void**)&p_ln, d_ln);
    cudaGetSymbolAddress((void**)&p_cntl, d_cntl);
    cudaGetSymbolAddress((void**)&p_cntu, d_cntu);
    cudaGetSymbolAddress((void**)&p_hl0, d_hrc_l0);
    cudaGetSymbolAddress((void**)&p_hl1, d_hrc_l1);
    cudaGetSymbolAddress((void**)&p_hl2, d_hrc_l2);
    cudaGetSymbolAddress((void**)&p_hu, d_hrc_u);
    float* p_hl[3] = {p_hl0, p_hl1, p_hl2};

    const int EGB = 1184;

#define EW1P(b, i) (eW1 + (size_t)((b)*3 + (i)) * 26 * HID)
#define EB1P(b, i) (eb1 + ((b)*3 + (i)) * HID)
#define EW2P(b, i) (eW2 + ((b)*3 + (i)) * HID)
#define EB2P(b, i) (eb2 + ((b)*3 + (i)))
#define NW1P(b, i) (nW1 + (size_t)((b)*3 + (i)) * 17 * HID)
#define NB1P(b, i) (nb1 + ((b)*3 + (i)) * HID)
#define NW2P(b, i) (nW2 + (size_t)((b)*3 + (i)) * HID * NF)
#define NB2P(b, i) (nb2 + ((b)*3 + (i)) * NF)
#define GWP(b, i) gW1 + (size_t)((b)*3 + (i)) * 17 * HID, gb1 + ((b)*3 + (i)) * HID, \
                  gW2 + (size_t)((b)*3 + (i)) * HID * NF, gb2 + ((b)*3 + (i)) * NF

    k_zero<<<NPB, 256>>>(EB1P(0, 0), NB1P(0, 0));
    k_setup<<<EBC + 3 * NPB, 256>>>(lrow, urow, x, EW1P(0, 0), EW1P(0, 1), EW1P(0, 2));

    for (int i = 0; i < 3; i++) {
        const float* le_prev = (i == 0) ? lattr : p_le;
        const float* ue_prev = (i == 0) ? uattr : p_ue;
        bool last = (i == 2);

        if (i == 0)
            k_edge<false, false, true><<<EGB, 256>>>(lrow, lcol, le_prev, lattr, EW1P(0, i), EW2P(0, i), EB2P(0, i), p_hl[i], p_le, outp);
        else if (!last)
            k_edge<true, false, true><<<EGB, 256>>>(lrow, lcol, le_prev, lattr, EW1P(0, i), EW2P(0, i), EB2P(0, i), p_hl[i], p_le, outp);
        else
            k_edge<true, true, true><<<EGB, 256>>>(lrow, lcol, le_prev, lattr, EW1P(0, i), EW2P(0, i), EB2P(0, i), p_hl[i], p_le, outp);

        k_node<true><<<NHB, 128>>>(x, p_cntl, NW1P(0, i), NW2P(0, i), NB2P(0, i), EW1P(1, i),
                                   GWP(0, i), EW1P(1, i), EB1P(1, i), NW1P(1, i), NB1P(1, i));

        if (!last)
            k_edge<false, false, true><<<EGB, 256>>>(urow, ucol, ue_prev, uattr, EW1P(1, i), EW2P(1, i), EB2P(1, i), p_hu, p_ue, outp);
        else
            k_edge<false, true, false><<<EGB, 256>>>(urow, ucol, ue_prev, uattr, EW1P(1, i), EW2P(1, i), EB2P(1, i), p_hu, p_ue,
                                                     outp + E_EDGES);

        if (!last)
            k_node<false><<<NHB, 128>>>(p_ln, p_cntu, NW1P(1, i), NW2P(1, i), NB2P(1, i), EW1P(1, i),
                                        GWP(1, i), EW1P(0, i + 1), EB1P(0, i + 1), NW1P(0, i + 1), NB1P(0, i + 1));
    }

#undef EW1P
#undef EB1P
#undef EW2P
#undef EB2P
#undef NW1P
#undef NB1P
#undef NW2P
#undef NB2P
#undef GWP
}

// round 17
// speedup vs baseline: 1.5833x; 1.0886x over previous
#include <cuda_runtime.h>
#include <cuda_fp16.h>
#include <math.h>

#define N_NODES 100000
#define E_EDGES 1100000
#define HID 32
#define GF 8
#define NF 8

#define EBC ((E_EDGES + 255) / 256)   // edge-count blocks
#define NPB ((N_NODES + 255) / 256)   // per-node prep blocks (256 thr)
#define NHB 391                        // node blocks: 128 thr, 2 nodes/thread
#define NSPLIT 50048                   // second node = v + NSPLIT

// ---------------- persistent device scratch ----------------
// hrc tables in fp16: [hr(32) | hc(32)] halves per node = 128 B/node (one line!)
__device__ __align__(16) __half d_hrc_l0[(size_t)N_NODES * 64];
__device__ __align__(16) __half d_hrc_l1[(size_t)N_NODES * 64];
__device__ __align__(16) __half d_hrc_l2[(size_t)N_NODES * 64];
__device__ __align__(16) __half d_hrc_u[(size_t)N_NODES * 64];
__device__ __align__(16) float d_le[E_EDGES];
__device__ __align__(16) float d_ue[E_EDGES];
__device__ __align__(16) float d_ln[N_NODES * NF];
__device__ float d_agg[N_NODES];
__device__ float d_cntl[N_NODES];
__device__ float d_cntu[N_NODES];
__device__ float d_g[GF];
__device__ float d_nsum[GF];
__device__ float d_esum;
__device__ float d_hbase_e[HID];
__device__ float d_hbase_n[HID];
__device__ unsigned d_ncnt;

__inline__ __device__ float warpAllSum(float v) {
#pragma unroll
    for (int o = 16; o > 0; o >>= 1) v += __shfl_xor_sync(0xffffffffu, v, o);
    return v;
}

__inline__ __device__ void l2_prefetch(const void* p) {
    asm volatile("prefetch.global.L2 [%0];" :: "l"(p));
}

// pack 8 floats -> uint4 of halves
__inline__ __device__ uint4 pack8h(const float* t) {
    uint4 pk;
    __half2* ph = reinterpret_cast<__half2*>(&pk);
    ph[0] = __floats2half2_rn(t[0], t[1]);
    ph[1] = __floats2half2_rn(t[2], t[3]);
    ph[2] = __floats2half2_rn(t[4], t[5]);
    ph[3] = __floats2half2_rn(t[6], t[7]);
    return pk;
}

// load 4 halves at p (8B aligned) -> float4
__inline__ __device__ float4 load4h(const __half* p) {
    uint2 raw = *reinterpret_cast<const uint2*>(p);
    float2 a = __half22float2(*reinterpret_cast<__half2*>(&raw.x));
    float2 b = __half22float2(*reinterpret_cast<__half2*>(&raw.y));
    return make_float4(a.x, a.y, b.x, b.y);
}

// ---------------- init ----------------
__global__ void k_zero(const float* __restrict__ eb1_0, const float* __restrict__ nb1_0) {
    int i = blockIdx.x * blockDim.x + threadIdx.x;
    if (i < N_NODES) {
        d_agg[i] = 0.f;
        d_cntl[i] = 0.f;
        d_cntu[i] = 0.f;
    }
    if (blockIdx.x == 0) {
        int j = threadIdx.x;
        if (j < HID) {
            d_hbase_e[j] = eb1_0[j];
            d_hbase_n[j] = nb1_0[j];
        }
        if (j < GF) { d_g[j] = 0.f; d_nsum[j] = 0.f; }
        if (j == 0) { d_esum = 0.f; d_ncnt = 0u; }
    }
}

// ---------------- prep body: hr = x @ W1[8:16], hc = x @ W1[16:24] -> fp16 ----------------
__device__ __forceinline__ void prep_body(int pb, int tid, float* sW,
                                          const float* __restrict__ xn,
                                          const float* __restrict__ W1,
                                          __half* __restrict__ hrc) {
    for (int i = tid; i < 16 * HID; i += 256) sW[i] = W1[8 * HID + i];
    __syncthreads();

    int v = pb * 256 + tid;
    if (v >= N_NODES) return;
    const float4* xp = reinterpret_cast<const float4*>(xn + (size_t)v * 8);
    float4 x0 = xp[0], x1 = xp[1];
    float xv[8] = {x0.x, x0.y, x0.z, x0.w, x1.x, x1.y, x1.z, x1.w};

    float h[HID];
    uint4* dst = reinterpret_cast<uint4*>(hrc + (size_t)v * 64);
#pragma unroll
    for (int hf = 0; hf < 2; hf++) {
#pragma unroll
        for (int j = 0; j < HID; j++) h[j] = 0.f;
#pragma unroll
        for (int k = 0; k < 8; k++) {
            float val = xv[k];
            const float4* wr = reinterpret_cast<const float4*>(&sW[(hf * 8 + k) * HID]);
#pragma unroll
            for (int j4 = 0; j4 < HID / 4; j4++) {
                float4 w = wr[j4];
                h[j4 * 4 + 0] = fmaf(val, w.x, h[j4 * 4 + 0]);
                h[j4 * 4 + 1] = fmaf(val, w.y, h[j4 * 4 + 1]);
                h[j4 * 4 + 2] = fmaf(val, w.z, h[j4 * 4 + 2]);
                h[j4 * 4 + 3] = fmaf(val, w.w, h[j4 * 4 + 3]);
            }
        }
        // 32 halves = 64 B = 4 uint4
#pragma unroll
        for (int q = 0; q < 4; q++) dst[hf * 4 + q] = pack8h(&h[q * 8]);
    }
}

// ---------------- setup mega-kernel ----------------
__global__ __launch_bounds__(256) void k_setup(const int* __restrict__ lrow,
                                               const int* __restrict__ urow,
                                               const float* __restrict__ x,
                                               const float* __restrict__ eW1_0,
                                               const float* __restrict__ eW1_1,
                                               const float* __restrict__ eW1_2) {
    __shared__ __align__(16) float sW[16 * HID];
    int bid = blockIdx.x;
    int tid = threadIdx.x;
    if (bid < EBC) {
        int e = bid * 256 + tid;
        if (e < E_EDGES) {
            atomicAdd(&d_cntl[lrow[e]], 1.0f);
            atomicAdd(&d_cntu[urow[e]], 1.0f);
        }
    } else {
        int t = bid - EBC;
        int layer = t / NPB;
        int pb = t % NPB;
        const float* W1 = (layer == 0) ? eW1_0 : (layer == 1) ? eW1_1 : eW1_2;
        __half* hrc = (layer == 0) ? d_hrc_l0 : (layer == 1) ? d_hrc_l1 : d_hrc_l2;
        prep_body(pb, tid, sW, x, W1, hrc);
    }
}

// ---------------- edge kernel: 8 lanes/edge, 4 edges per group-iteration, fp16 gather ----------------
template <bool HAS_SKIP, bool WRITE_OUT, bool DO_AGG>
__global__ __launch_bounds__(256) void k_edge(
    const int* __restrict__ row, const int* __restrict__ col,
    const float* __restrict__ eprev, const float* __restrict__ eskip,
    const float* __restrict__ W1,    // 26x32 (rows 24,25 used)
    const float* __restrict__ W2,    // 32
    const float* __restrict__ B2,    // 1
    const __half* __restrict__ hrc,  // N x 64 fp16 table
    float* __restrict__ ebuf,
    float* __restrict__ outp) {
    __shared__ float sred[8];
    int tid = threadIdx.x;
    int c = tid & 7;
    int g = tid >> 3;

    float base[4], w24[4], w25[4], w2[4];
#pragma unroll
    for (int i = 0; i < 4; i++) {
        base[i] = d_hbase_e[c * 4 + i];
        w24[i] = __ldg(&W1[24 * HID + c * 4 + i]);
        w25[i] = HAS_SKIP ? __ldg(&W1[25 * HID + c * 4 + i]) : 0.f;
        w2[i] = __ldg(&W2[c * 4 + i]);
    }
    float b2 = __ldg(B2);

    float esum_local = 0.f;
    const int step = gridDim.x * 128;
    for (int e0 = (blockIdx.x * 32 + g) * 4; e0 < E_EDGES; e0 += step) {
        int4 rr = *reinterpret_cast<const int4*>(&row[e0]);
        int4 cc = *reinterpret_cast<const int4*>(&col[e0]);
        float4 epv = *reinterpret_cast<const float4*>(&eprev[e0]);
        float4 esv = HAS_SKIP ? *reinterpret_cast<const float4*>(&eskip[e0])
                              : make_float4(0.f, 0.f, 0.f, 0.f);
        int r[4] = {rr.x, rr.y, rr.z, rr.w};
        int cl[4] = {cc.x, cc.y, cc.z, cc.w};
        float ep[4] = {epv.x, epv.y, epv.z, epv.w};
        float es[4] = {esv.x, esv.y, esv.z, esv.w};

        float4 hr[4], hc[4];
#pragma unroll
        for (int i = 0; i < 4; i++) {
            hr[i] = load4h(hrc + (size_t)(unsigned)r[i] * 64 + c * 4);
            hc[i] = load4h(hrc + (size_t)(unsigned)cl[i] * 64 + 32 + c * 4);
        }

        float p[4];
#pragma unroll
        for (int i = 0; i < 4; i++) {
            float t, q = 0.f;
            t = base[0] + hr[i].x + hc[i].x; t = fmaf(ep[i], w24[0], t); if (HAS_SKIP) t = fmaf(es[i], w25[0], t);
            q = fmaf(fmaxf(t, 0.f), w2[0], q);
            t = base[1] + hr[i].y + hc[i].y; t = fmaf(ep[i], w24[1], t); if (HAS_SKIP) t = fmaf(es[i], w25[1], t);
            q = fmaf(fmaxf(t, 0.f), w2[1], q);
            t = base[2] + hr[i].z + hc[i].z; t = fmaf(ep[i], w24[2], t); if (HAS_SKIP) t = fmaf(es[i], w25[2], t);
            q = fmaf(fmaxf(t, 0.f), w2[2], q);
            t = base[3] + hr[i].w + hc[i].w; t = fmaf(ep[i], w24[3], t); if (HAS_SKIP) t = fmaf(es[i], w25[3], t);
            q = fmaf(fmaxf(t, 0.f), w2[3], q);
            p[i] = q;
        }

#pragma unroll
        for (int i = 0; i < 4; i++) p[i] += __shfl_down_sync(0xffffffffu, p[i], 4);
#pragma unroll
        for (int i = 0; i < 4; i++) p[i] += __shfl_down_sync(0xffffffffu, p[i], 2);
#pragma unroll
        for (int i = 0; i < 4; i++) p[i] += __shfl_down_sync(0xffffffffu, p[i], 1);

        if (c == 0) {
            float o[4];
#pragma unroll
            for (int i = 0; i < 4; i++) o[i] = p[i] + b2;
            *reinterpret_cast<float4*>(&ebuf[e0]) = make_float4(o[0], o[1], o[2], o[3]);
            if (DO_AGG) {
#pragma unroll
                for (int i = 0; i < 4; i++) {
                    atomicAdd(&d_agg[r[i]], o[i]);
                    esum_local += o[i];
                }
            }
            if (WRITE_OUT) {
                float q[4];
#pragma unroll
                for (int i = 0; i < 4; i++) q[i] = (r[i] == cl[i]) ? expf(o[i]) : o[i];
                *reinterpret_cast<float4*>(&outp[e0]) = make_float4(q[0], q[1], q[2], q[3]);
            }
        }
    }

    if (DO_AGG) {
        float s = warpAllSum(esum_local);
        if ((tid & 31) == 0) sred[tid >> 5] = s;
        __syncthreads();
        if (tid < 8) {
            float v = sred[tid];
            v += __shfl_xor_sync(0xffu, v, 1);
            v += __shfl_xor_sync(0xffu, v, 2);
            v += __shfl_xor_sync(0xffu, v, 4);
            if (tid == 0) atomicAdd(&d_esum, v);
        }
    }
}

// ---------------- node kernel: 128 thr, 2 nodes/thread, register-chunked ----------------
template <bool FUSE_U>
__global__ __launch_bounds__(128, 4) void k_node(
    const float* __restrict__ xn,   // N x 8 (x or ln)
    const float* __restrict__ cnt,  // N
    const float* __restrict__ W1,   // 17 x 32 (rows 8..16 used)
    const float* __restrict__ W2,   // 32 x 8
    const float* __restrict__ B2,   // 8
    const float* __restrict__ uW1,  // next (upper) edge W1, rows 8..24 (FUSE_U)
    const float* __restrict__ gW1, const float* __restrict__ gB1,
    const float* __restrict__ gW2, const float* __restrict__ gB2,
    const float* __restrict__ neW1, const float* __restrict__ neB1,
    const float* __restrict__ nnW1, const float* __restrict__ nnB1) {
    __shared__ __align__(16) float sW1[9 * HID];
    __shared__ __align__(16) float sW2[HID * NF];
    __shared__ __align__(16) float sUW[16 * HID];
    __shared__ float sB2[NF];
    __shared__ float sbase[HID];
    __shared__ float sred[4][NF];
    __shared__ int s_last;

    int tid = threadIdx.x;
    for (int i = tid; i < 9 * HID; i += 128) sW1[i] = W1[8 * HID + i];
    for (int i = tid; i < HID * NF; i += 128) sW2[i] = W2[i];
    if (FUSE_U)
        for (int i = tid; i < 16 * HID; i += 128) sUW[i] = uW1[8 * HID + i];
    if (tid < HID) sbase[tid] = d_hbase_n[tid];
    if (tid < NF) sB2[tid] = B2[tid];
    // warm L2 for the fused-global tail
    if (tid < 17) l2_prefetch(gW1 + tid * 32);
    else if (tid < 25) l2_prefetch(gW2 + (tid - 17) * 32);
    else if (tid < 33) l2_prefetch(neW1 + (tid - 25) * 32);
    else if (tid < 41) l2_prefetch(nnW1 + (tid - 33) * 32);
    else if (tid == 41) l2_prefetch(gB1);
    else if (tid == 42) l2_prefetch(neB1);
    else if (tid == 43) l2_prefetch(nnB1);
    else if (tid == 44) l2_prefetch(gB2);
    __syncthreads();

    int vA = blockIdx.x * 128 + tid;   // always < NSPLIT <= N_NODES
    int vB = vA + NSPLIT;
    bool valB = (vB < N_NODES);

    // ---- inputs for both nodes ----
    const float4* xpA = reinterpret_cast<const float4*>(xn + (size_t)vA * 8);
    float4 xA0 = xpA[0], xA1 = xpA[1];
    float aA = d_agg[vA] / fmaxf(cnt[vA], 1.0f);
    d_agg[vA] = 0.f;
    float4 xB0 = make_float4(0.f, 0.f, 0.f, 0.f), xB1 = xB0;
    float aB = 0.f;
    if (valB) {
        const float4* xpB = reinterpret_cast<const float4*>(xn + (size_t)vB * 8);
        xB0 = xpB[0]; xB1 = xpB[1];
        aB = d_agg[vB] / fmaxf(cnt[vB], 1.0f);
        d_agg[vB] = 0.f;
    }
    float xvA[8] = {xA0.x, xA0.y, xA0.z, xA0.w, xA1.x, xA1.y, xA1.z, xA1.w};
    float xvB[8] = {xB0.x, xB0.y, xB0.z, xB0.w, xB1.x, xB1.y, xB1.z, xB1.w};

    // ---- layers 1+2 in two 16-unit halves ----
    float oA[NF], oB[NF];
#pragma unroll
    for (int f = 0; f < NF; f++) { oA[f] = sB2[f]; oB[f] = sB2[f]; }
#pragma unroll
    for (int hf = 0; hf < 2; hf++) {
        float hA[16], hB[16];
#pragma unroll
        for (int m = 0; m < 16; m++) {
            float b = sbase[hf * 16 + m];
            hA[m] = b; hB[m] = b;
        }
#pragma unroll
        for (int k = 0; k < 9; k++) {
            float va = (k < 8) ? xvA[k] : aA;
            float vb = (k < 8) ? xvB[k] : aB;
            const float4* wr = reinterpret_cast<const float4*>(&sW1[k * HID + hf * 16]);
#pragma unroll
            for (int m4 = 0; m4 < 4; m4++) {
                float4 w = wr[m4];
                hA[m4 * 4 + 0] = fmaf(va, w.x, hA[m4 * 4 + 0]);
                hB[m4 * 4 + 0] = fmaf(vb, w.x, hB[m4 * 4 + 0]);
                hA[m4 * 4 + 1] = fmaf(va, w.y, hA[m4 * 4 + 1]);
                hB[m4 * 4 + 1] = fmaf(vb, w.y, hB[m4 * 4 + 1]);
                hA[m4 * 4 + 2] = fmaf(va, w.z, hA[m4 * 4 + 2]);
                hB[m4 * 4 + 2] = fmaf(vb, w.z, hB[m4 * 4 + 2]);
                hA[m4 * 4 + 3] = fmaf(va, w.w, hA[m4 * 4 + 3]);
                hB[m4 * 4 + 3] = fmaf(vb, w.w, hB[m4 * 4 + 3]);
            }
        }
#pragma unroll
        for (int jj = 0; jj < 16; jj++) {
            float rA = fmaxf(hA[jj], 0.f);
            float rB = fmaxf(hB[jj], 0.f);
            const float4* wr = reinterpret_cast<const float4*>(&sW2[(hf * 16 + jj) * NF]);
            float4 w0 = wr[0], w1 = wr[1];
            oA[0] = fmaf(rA, w0.x, oA[0]); oB[0] = fmaf(rB, w0.x, oB[0]);
            oA[1] = fmaf(rA, w0.y, oA[1]); oB[1] = fmaf(rB, w0.y, oB[1]);
            oA[2] = fmaf(rA, w0.z, oA[2]); oB[2] = fmaf(rB, w0.z, oB[2]);
            oA[3] = fmaf(rA, w0.w, oA[3]); oB[3] = fmaf(rB, w0.w, oB[3]);
            oA[4] = fmaf(rA, w1.x, oA[4]); oB[4] = fmaf(rB, w1.x, oB[4]);
            oA[5] = fmaf(rA, w1.y, oA[5]); oB[5] = fmaf(rB, w1.y, oB[5]);
            oA[6] = fmaf(rA, w1.z, oA[6]); oB[6] = fmaf(rB, w1.z, oB[6]);
            oA[7] = fmaf(rA, w1.w, oA[7]); oB[7] = fmaf(rB, w1.w, oB[7]);
        }
    }

    if (FUSE_U) {
        float4* lnA = reinterpret_cast<float4*>(&d_ln[(size_t)vA * 8]);
        lnA[0] = make_float4(oA[0], oA[1], oA[2], oA[3]);
        lnA[1] = make_float4(oA[4], oA[5], oA[6], oA[7]);
        if (valB) {
            float4* lnB = reinterpret_cast<float4*>(&d_ln[(size_t)vB * 8]);
            lnB[0] = make_float4(oB[0], oB[1], oB[2], oB[3]);
            lnB[1] = make_float4(oB[4], oB[5], oB[6], oB[7]);
        }
        // fp16 table build in four 16-col chunks
        uint4* dstA = reinterpret_cast<uint4*>(d_hrc_u + (size_t)vA * 64);
        uint4* dstB = reinterpret_cast<uint4*>(d_hrc_u + (size_t)vB * 64);
#pragma unroll
        for (int hf = 0; hf < 2; hf++) {
#pragma unroll
            for (int cnk = 0; cnk < 2; cnk++) {
                float tA[16], tB[16];
#pragma unroll
                for (int m = 0; m < 16; m++) { tA[m] = 0.f; tB[m] = 0.f; }
#pragma unroll
                for (int k = 0; k < 8; k++) {
                    float va = oA[k], vb = oB[k];
                    const float4* wr = reinterpret_cast<const float4*>(&sUW[(hf * 8 + k) * HID + cnk * 16]);
#pragma unroll
                    for (int m4 = 0; m4 < 4; m4++) {
                        float4 w = wr[m4];
                        tA[m4 * 4 + 0] = fmaf(va, w.x, tA[m4 * 4 + 0]);
                        tB[m4 * 4 + 0] = fmaf(vb, w.x, tB[m4 * 4 + 0]);
                        tA[m4 * 4 + 1] = fmaf(va, w.y, tA[m4 * 4 + 1]);
                        tB[m4 * 4 + 1] = fmaf(vb, w.y, tB[m4 * 4 + 1]);
                        tA[m4 * 4 + 2] = fmaf(va, w.z, tA[m4 * 4 + 2]);
                        tB[m4 * 4 + 2] = fmaf(vb, w.z, tB[m4 * 4 + 2]);
                        tA[m4 * 4 + 3] = fmaf(va, w.w, tA[m4 * 4 + 3]);
                        tB[m4 * 4 + 3] = fmaf(vb, w.w, tB[m4 * 4 + 3]);
                    }
                }
                // 16 floats -> 16 halves = 2 uint4
                dstA[hf * 4 + cnk * 2 + 0] = pack8h(&tA[0]);
                dstA[hf * 4 + cnk * 2 + 1] = pack8h(&tA[8]);
                if (valB) {
                    dstB[hf * 4 + cnk * 2 + 0] = pack8h(&tB[0]);
                    dstB[hf * 4 + cnk * 2 + 1] = pack8h(&tB[8]);
                }
            }
        }
    }

    // ---- block nsum reduce (both nodes) + fused global update ----
#pragma unroll
    for (int f = 0; f < NF; f++) {
        float contrib = oA[f] + (valB ? oB[f] : 0.f);
        float s = warpAllSum(contrib);
        if ((tid & 31) == 0) sred[tid >> 5][f] = s;
    }
    __syncthreads();
    if (tid < NF) {
        float s = sred[0][tid] + sred[1][tid] + sred[2][tid] + sred[3][tid];
        atomicAdd(&d_nsum[tid], s);
    }

    __syncthreads();
    if (tid == 0) {
        __threadfence();
        unsigned old = atomicAdd(&d_ncnt, 1u);
        s_last = (old == gridDim.x - 1) ? 1 : 0;
    }
    __syncthreads();
    if (s_last && tid < 32) {
        int j = tid;
        float in[17];
#pragma unroll
        for (int f = 0; f < NF; f++) in[f] = __ldcg(&d_nsum[f]) / (float)N_NODES;
        in[8] = __ldcg(&d_esum) / (float)E_EDGES;
#pragma unroll
        for (int f = 0; f < GF; f++) in[9 + f] = __ldcg(&d_g[f]);

        float h = gB1[j];
#pragma unroll
        for (int k = 0; k < 17; k++) h = fmaf(in[k], gW1[k * HID + j], h);
        h = fmaxf(h, 0.f);

        float gnew[GF];
#pragma unroll
        for (int f = 0; f < GF; f++) gnew[f] = __ldg(&gB2[f]) + warpAllSum(h * gW2[j * NF + f]);

        float be = neB1[j], bn = nnB1[j];
#pragma unroll
        for (int f = 0; f < GF; f++) {
            be = fmaf(gnew[f], neW1[f * HID + j], be);
            bn = fmaf(gnew[f], nnW1[f * HID + j], bn);
        }
        d_hbase_e[j] = be;
        d_hbase_n[j] = bn;

        if (j < GF) {
            d_g[j] = gnew[j];
            d_nsum[j] = 0.f;
        }
        if (j == 0) {
            d_esum = 0.f;
            d_ncnt = 0u;
        }
    }
}

// ---------------- host launch ----------------
extern "C" void kernel_launch(void* const* d_in, const int* in_sizes, int n_in,
                              void* d_out, int out_size) {
    const float* x = (const float*)d_in[0];
    const int* lei = (const int*)d_in[1];
    const int* uei = (const int*)d_in[2];
    const float* lattr = (const float*)d_in[3];
    const float* uattr = (const float*)d_in[4];
    const float* eW1 = (const float*)d_in[5];
    const float* eb1 = (const float*)d_in[6];
    const float* eW2 = (const float*)d_in[7];
    const float* eb2 = (const float*)d_in[8];
    const float* nW1 = (const float*)d_in[9];
    const float* nb1 = (const float*)d_in[10];
    const float* nW2 = (const float*)d_in[11];
    const float* nb2 = (const float*)d_in[12];
    const float* gW1 = (const float*)d_in[13];
    const float* gb1 = (const float*)d_in[14];
    const float* gW2 = (const float*)d_in[15];
    const float* gb2 = (const float*)d_in[16];
    float* outp = (float*)d_out;

    const int* lrow = lei;
    const int* lcol = lei + E_EDGES;
    const int* urow = uei;
    const int* ucol = uei + E_EDGES;

    float *p_le, *p_ue, *p_ln, *p_cntl, *p_cntu;
    __half *p_hl0, *p_hl1, *p_hl2, *p_hu;
    cudaGetSymbolAddress((void**)&p_le, d_le);
    cudaGetSymbolAddress((void**)&p_ue, d_ue);
    cudaGetSymbolAddress((void**)&p_ln, d_ln);
    cudaGetSymbolAddress((void**)&p_cntl, d_cntl);
    cudaGetSymbolAddress((void**)&p_cntu, d_cntu);
    cudaGetSymbolAddress((void**)&p_hl0, d_hrc_l0);
    cudaGetSymbolAddress((void**)&p_hl1, d_hrc_l1);
    cudaGetSymbolAddress((void**)&p_hl2, d_hrc_l2);
    cudaGetSymbolAddress((void**)&p_hu, d_hrc_u);
    __half* p_hl[3] = {p_hl0, p_hl1, p_hl2};

    const int EGB = 1184;

#define EW1P(b, i) (eW1 + (size_t)((b)*3 + (i)) * 26 * HID)
#define EB1P(b, i) (eb1 + ((b)*3 + (i)) * HID)
#define EW2P(b, i) (eW2 + ((b)*3 + (i)) * HID)
#define EB2P(b, i) (eb2 + ((b)*3 + (i)))
#define NW1P(b, i) (nW1 + (size_t)((b)*3 + (i)) * 17 * HID)
#define NB1P(b, i) (nb1 + ((b)*3 + (i)) * HID)
#define NW2P(b, i) (nW2 + (size_t)((b)*3 + (i)) * HID * NF)
#define NB2P(b, i) (nb2 + ((b)*3 + (i)) * NF)
#define GWP(b, i) gW1 + (size_t)((b)*3 + (i)) * 17 * HID, gb1 + ((b)*3 + (i)) * HID, \
                  gW2 + (size_t)((b)*3 + (i)) * HID * NF, gb2 + ((b)*3 + (i)) * NF

    k_zero<<<NPB, 256>>>(EB1P(0, 0), NB1P(0, 0));
    k_setup<<<EBC + 3 * NPB, 256>>>(lrow, urow, x, EW1P(0, 0), EW1P(0, 1), EW1P(0, 2));

    for (int i = 0; i < 3; i++) {
        const float* le_prev = (i == 0) ? lattr : p_le;
        const float* ue_prev = (i == 0) ? uattr : p_ue;
        bool last = (i == 2);

        if (i == 0)
            k_edge<false, false, true><<<EGB, 256>>>(lrow, lcol, le_prev, lattr, EW1P(0, i), EW2P(0, i), EB2P(0, i), p_hl[i], p_le, outp);
        else if (!last)
            k_edge<true, false, true><<<EGB, 256>>>(lrow, lcol, le_prev, lattr, EW1P(0, i), EW2P(0, i), EB2P(0, i), p_hl[i], p_le, outp);
        else
            k_edge<true, true, true><<<EGB, 256>>>(lrow, lcol, le_prev, lattr, EW1P(0, i), EW2P(0, i), EB2P(0, i), p_hl[i], p_le, outp);

        k_node<true><<<NHB, 128>>>(x, p_cntl, NW1P(0, i), NW2P(0, i), NB2P(0, i), EW1P(1, i),
                                   GWP(0, i), EW1P(1, i), EB1P(1, i), NW1P(1, i), NB1P(1, i));

        if (!last)
            k_edge<false, false, true><<<EGB, 256>>>(urow, ucol, ue_prev, uattr, EW1P(1, i), EW2P(1, i), EB2P(1, i), p_hu, p_ue, outp);
        else
            k_edge<false, true, false><<<EGB, 256>>>(urow, ucol, ue_prev, uattr, EW1P(1, i), EW2P(1, i), EB2P(1, i), p_hu, p_ue,
                                                     outp + E_EDGES);

        if (!last)
            k_node<false><<<NHB, 128>>>(p_ln, p_cntu, NW1P(1, i), NW2P(1, i), NB2P(1, i), EW1P(1, i),
                                        GWP(1, i), EW1P(0, i + 1), EB1P(0, i + 1), NW1P(0, i + 1), NB1P(0, i + 1));
    }

#undef EW1P
#undef EB1P
#undef EW2P
#undef EB2P
#undef NW1P
#undef NB1P
#undef NW2P
#undef NB2P
#undef GWP
}